// round 4
// baseline (speedup 1.0000x reference)
#include <cuda_runtime.h>
#include <math.h>

// ---------------------------------------------------------------------------
// ElectronicEmbedding (SpookyNet) fused kernel set.
//
// Algebra: q@Wk collapses (k is rank-1 per batch) -> dot_n = cf_b*(x_n.u + c0)/16
//          y is rank-1 per row: y[n,f] = s_n * Wv[f]
// Heavy part: residual MLP chain = 5 GEMMs [N,256]x[256,256] with silu,
// fused into one tile kernel (64 rows per CTA, SMEM resident, FFMA2).
// ---------------------------------------------------------------------------

#define FDIM 256
#define TM 64
#define KCHUNK 16
#define SW_STRIDE 260   // padded row stride for weight staging
#define MAXN 200704
#define MAXB 4096

__device__ float g_u[FDIM];      // Wq^T @ Wk
__device__ float g_c0;           // bq . Wk
__device__ float g_cf[MAXB];     // |E|/max(|E|,1)
__device__ float g_ev[MAXB];     // |E|
__device__ float g_anorm[MAXB];  // segment sum of a
__device__ float g_a[MAXN];      // per-atom softplus attention weight
__device__ int   g_seg64;        // 1 if batch_seg is int64, 0 if int32

// -------- seg accessor: dtype decided at runtime, index always clamped -----
__device__ __forceinline__ int get_seg(const void* seg, int n) {
    int b;
    if (g_seg64) b = (int)((const long long*)seg)[n];
    else         b = ((const int*)seg)[n];
    // defensive clamp: a wrong dtype guess must not become an OOB access
    if (b < 0) b = 0;
    if (b >= MAXB) b = MAXB - 1;
    return b;
}

// ---------------- packed f32x2 helpers (Blackwell FFMA2) -------------------
__device__ __forceinline__ unsigned long long packf2(float x, float y) {
    unsigned long long r;
    asm("mov.b64 %0, {%1, %2};" : "=l"(r)
        : "r"(__float_as_uint(x)), "r"(__float_as_uint(y)));
    return r;
}
__device__ __forceinline__ void unpackf2(unsigned long long v, float& x, float& y) {
    unsigned lo, hi;
    asm("mov.b64 {%0, %1}, %2;" : "=r"(lo), "=r"(hi) : "l"(v));
    x = __uint_as_float(lo);
    y = __uint_as_float(hi);
}
__device__ __forceinline__ void fma2(unsigned long long& d,
                                     unsigned long long a,
                                     unsigned long long b) {
    asm("fma.rn.f32x2 %0, %1, %2, %0;" : "+l"(d) : "l"(a), "l"(b));
}

__device__ __forceinline__ float siluf(float x) {
    return x * (1.0f / (1.0f + __expf(-x)));
}
__device__ __forceinline__ float4 silu4(float4 v) {
    return make_float4(siluf(v.x), siluf(v.y), siluf(v.z), siluf(v.w));
}

// ---------------------------------------------------------------------------
// Kernel 0: detect seg dtype. Reading int32[0..N-1] is safe for both dtypes
// (4N bytes <= buffer size). int64 little-endian: word N-1 is a high word = 0
// while word N-2 > 0 (sorted seg, value ~B-1). int32: word N-1 = seg[N-1] > 0.
// ---------------------------------------------------------------------------
__global__ void detect_kernel(const int* __restrict__ seg32, int N) {
    int last = seg32[N - 1];
    int prev = seg32[N - 2];
    g_seg64 = (last == 0 && prev > 0) ? 1 : 0;
}

// ---------------------------------------------------------------------------
// Kernel A: prep. block 0 computes u, c0; other blocks per-batch factors.
// ---------------------------------------------------------------------------
__global__ void prep_kernel(const float* __restrict__ Wq,
                            const float* __restrict__ Wk,
                            const float* __restrict__ bq,
                            const float* __restrict__ E, int B) {
    int tid = threadIdx.x;
    if (blockIdx.x == 0) {
        float s = 0.0f;
#pragma unroll 8
        for (int f = 0; f < FDIM; f++)
            s = fmaf(Wk[f], Wq[f * FDIM + tid], s);
        g_u[tid] = s;
        if (tid == 0) {
            float c = 0.0f;
            for (int f = 0; f < FDIM; f++) c = fmaf(bq[f], Wk[f], c);
            g_c0 = c;
        }
    } else {
        int b = (blockIdx.x - 1) * 256 + tid;
        if (b < B) {
            float e = fabsf(E[b]);
            g_ev[b] = e;
            g_cf[b] = e / fmaxf(e, 1.0f);
            g_anorm[b] = 0.0f;
        }
    }
}

// ---------------------------------------------------------------------------
// Kernel B: per-atom dot (matvec) + softplus + atomic segment sum.
// One warp per row; 8 rows per 256-thread block.
// ---------------------------------------------------------------------------
__global__ void dot_kernel(const float* __restrict__ x,
                           const void* __restrict__ seg, int N) {
    __shared__ float su[FDIM];
    __shared__ float sc0;
    int tid = threadIdx.x;
    su[tid] = g_u[tid];
    if (tid == 0) sc0 = g_c0;
    __syncthreads();

    int wid = tid >> 5, lane = tid & 31;
    int n = blockIdx.x * 8 + wid;
    if (n >= N) return;

    const float4* xr = (const float4*)(x + (size_t)n * FDIM);
    float4 xa = xr[lane];
    float4 xb = xr[32 + lane];
    float4 u0 = *(const float4*)&su[4 * lane];
    float4 u1 = *(const float4*)&su[128 + 4 * lane];
    float p = xa.x * u0.x + xa.y * u0.y + xa.z * u0.z + xa.w * u0.w +
              xb.x * u1.x + xb.y * u1.y + xb.z * u1.z + xb.w * u1.w;
#pragma unroll
    for (int o = 16; o > 0; o >>= 1) p += __shfl_down_sync(0xffffffffu, p, o);

    if (lane == 0) {
        int b = get_seg(seg, n);
        float d = (p + sc0) * g_cf[b] * 0.0625f;  // /sqrt(256)
        // numerically stable softplus
        float a = fmaxf(d, 0.0f) + log1pf(expf(-fabsf(d)));
        g_a[n] = a;
        atomicAdd(&g_anorm[b], a);
    }
}

// ---------------------------------------------------------------------------
// Fused chain kernel: 64-row tile per CTA.
// Thread tile: 8 rows (ty*8..) x 8 cols (tx*4.. and 128+tx*4..).
// GEMM: t[m][f] = sum_g A[m][g] * W[f][g], W row-major [F][F].
// ---------------------------------------------------------------------------
__device__ __forceinline__ void gemm_tile(const float* __restrict__ gW,
                                          unsigned long long acc[8][4],
                                          const float* __restrict__ sA,
                                          float* __restrict__ sW,
                                          int tx, int ty, int tid) {
#pragma unroll
    for (int i = 0; i < 8; i++)
#pragma unroll
        for (int j = 0; j < 4; j++) acc[i][j] = 0ull;

    const float* aBase = sA + (ty * 8) * FDIM;
    const float4* gW4 = (const float4*)gW;

#pragma unroll 1
    for (int g0 = 0; g0 < FDIM; g0 += KCHUNK) {
        __syncthreads();  // previous chunk consumed / sA ready on entry
        // stage sW[gg][f] = W[f][g0+gg]
#pragma unroll
        for (int p = 0; p < 4; p++) {
            int e = p * 256 + tid;  // 0..1023
            int f = e >> 2;
            int q = e & 3;
            float4 v = gW4[f * (FDIM / 4) + (g0 >> 2) + q];
            float* d = sW + (q * 4) * SW_STRIDE + f;
            d[0] = v.x;
            d[SW_STRIDE] = v.y;
            d[2 * SW_STRIDE] = v.z;
            d[3 * SW_STRIDE] = v.w;
        }
        __syncthreads();

#pragma unroll
        for (int kk = 0; kk < KCHUNK; kk++) {
            const float* wr = sW + kk * SW_STRIDE;
            float4 w0 = *(const float4*)(wr + tx * 4);
            float4 w1 = *(const float4*)(wr + 128 + tx * 4);
            unsigned long long wp0 = packf2(w0.x, w0.y);
            unsigned long long wp1 = packf2(w0.z, w0.w);
            unsigned long long wp2 = packf2(w1.x, w1.y);
            unsigned long long wp3 = packf2(w1.z, w1.w);
#pragma unroll
            for (int i = 0; i < 8; i++) {
                float av = aBase[i * FDIM + g0 + kk];  // broadcast within warp
                unsigned long long aa = packf2(av, av);
                fma2(acc[i][0], aa, wp0);
                fma2(acc[i][1], aa, wp1);
                fma2(acc[i][2], aa, wp2);
                fma2(acc[i][3], aa, wp3);
            }
        }
    }
}

__global__ __launch_bounds__(256, 1)
void chain_kernel(const void* __restrict__ seg,
                  const float* __restrict__ Wv,
                  const float* __restrict__ Wres1,
                  const float* __restrict__ Wres2,
                  const float* __restrict__ Wout,
                  float* __restrict__ out, int N) {
    extern __shared__ float sm[];
    float* sH = sm;                              // TM*FDIM
    float* sA = sH + TM * FDIM;                  // TM*FDIM
    float* sW = sA + TM * FDIM;                  // KCHUNK*SW_STRIDE
    float* sv = sW + KCHUNK * SW_STRIDE;         // TM

    int tid = threadIdx.x;
    int tx = tid & 31, ty = tid >> 5;
    int r0 = blockIdx.x * TM;

    if (tid < TM) {
        int n = r0 + tid;
        float s = 0.0f;
        if (n < N) {
            int b = get_seg(seg, n);
            s = g_a[n] / (g_anorm[b] + 1e-8f) * g_ev[b];
        }
        sv[tid] = s;
    }
    __syncthreads();

    // h0[m,f] = s_m * Wv[f]; A = silu(h0)
    float4 wv0 = ((const float4*)Wv)[tx];
    float4 wv1 = ((const float4*)Wv)[32 + tx];
#pragma unroll
    for (int i = 0; i < 8; i++) {
        int r = ty * 8 + i;
        float s = sv[r];
        float4 h0 = make_float4(s * wv0.x, s * wv0.y, s * wv0.z, s * wv0.w);
        float4 h1 = make_float4(s * wv1.x, s * wv1.y, s * wv1.z, s * wv1.w);
        *(float4*)&sH[r * FDIM + tx * 4] = h0;
        *(float4*)&sH[r * FDIM + 128 + tx * 4] = h1;
        *(float4*)&sA[r * FDIM + tx * 4] = silu4(h0);
        *(float4*)&sA[r * FDIM + 128 + tx * 4] = silu4(h1);
    }
    // gemm_tile's leading __syncthreads makes sA visible to all.

    unsigned long long acc[8][4];

#pragma unroll 1
    for (int it = 0; it < 2; it++) {
        // t = silu(h) @ Wres1[it].T
        gemm_tile(Wres1 + it * FDIM * FDIM, acc, sA, sW, tx, ty, tid);
        __syncthreads();  // all sA reads done before overwrite
        // A = silu(t)
#pragma unroll
        for (int i = 0; i < 8; i++) {
            int r = ty * 8 + i;
            float4 v0, v1;
            unpackf2(acc[i][0], v0.x, v0.y);
            unpackf2(acc[i][1], v0.z, v0.w);
            unpackf2(acc[i][2], v1.x, v1.y);
            unpackf2(acc[i][3], v1.z, v1.w);
            *(float4*)&sA[r * FDIM + tx * 4] = silu4(v0);
            *(float4*)&sA[r * FDIM + 128 + tx * 4] = silu4(v1);
        }
        // h += A @ Wres2[it].T ; next A = silu(h)
        gemm_tile(Wres2 + it * FDIM * FDIM, acc, sA, sW, tx, ty, tid);
        __syncthreads();
#pragma unroll
        for (int i = 0; i < 8; i++) {
            int r = ty * 8 + i;
            float4 d0, d1;
            unpackf2(acc[i][0], d0.x, d0.y);
            unpackf2(acc[i][1], d0.z, d0.w);
            unpackf2(acc[i][2], d1.x, d1.y);
            unpackf2(acc[i][3], d1.z, d1.w);
            float4 h0 = *(float4*)&sH[r * FDIM + tx * 4];
            float4 h1 = *(float4*)&sH[r * FDIM + 128 + tx * 4];
            h0.x += d0.x; h0.y += d0.y; h0.z += d0.z; h0.w += d0.w;
            h1.x += d1.x; h1.y += d1.y; h1.z += d1.z; h1.w += d1.w;
            *(float4*)&sH[r * FDIM + tx * 4] = h0;
            *(float4*)&sH[r * FDIM + 128 + tx * 4] = h1;
            *(float4*)&sA[r * FDIM + tx * 4] = silu4(h0);
            *(float4*)&sA[r * FDIM + 128 + tx * 4] = silu4(h1);
        }
    }

    // out = silu(h) @ Wout.T  (A already holds silu(h))
    gemm_tile(Wout, acc, sA, sW, tx, ty, tid);

#pragma unroll
    for (int i = 0; i < 8; i++) {
        int n = r0 + ty * 8 + i;
        if (n < N) {
            float4 o0, o1;
            unpackf2(acc[i][0], o0.x, o0.y);
            unpackf2(acc[i][1], o0.z, o0.w);
            unpackf2(acc[i][2], o1.x, o1.y);
            unpackf2(acc[i][3], o1.z, o1.w);
            *(float4*)&out[(size_t)n * FDIM + tx * 4] = o0;
            *(float4*)&out[(size_t)n * FDIM + 128 + tx * 4] = o1;
        }
    }
}

// ---------------------------------------------------------------------------
extern "C" void kernel_launch(void* const* d_in, const int* in_sizes, int n_in,
                              void* d_out, int out_size) {
    // Input order per reference: x, E, num_batch(scalar, maybe present),
    // batch_seg, Wq, bq, Wk, Wv, Wres1, Wres2, Wout.
    // If the num_batch scalar occupies a slot, in_sizes[2]==1; otherwise
    // slot 2 is batch_seg (size N).
    int base = (n_in >= 11 && in_sizes[2] == 1) ? 1 : 0;

    const float* x     = (const float*)d_in[0];
    const float* E     = (const float*)d_in[1];
    const void*  seg   = d_in[2 + base];
    const float* Wq    = (const float*)d_in[3 + base];
    const float* bq    = (const float*)d_in[4 + base];
    const float* Wk    = (const float*)d_in[5 + base];
    const float* Wv    = (const float*)d_in[6 + base];
    const float* Wres1 = (const float*)d_in[7 + base];
    const float* Wres2 = (const float*)d_in[8 + base];
    const float* Wout  = (const float*)d_in[9 + base];

    int N = in_sizes[0] / FDIM;
    int B = in_sizes[1];
    if (N > MAXN) N = MAXN;
    if (B > MAXB) B = MAXB;

    detect_kernel<<<1, 1>>>((const int*)seg, N);
    prep_kernel<<<1 + (B + 255) / 256, 256>>>(Wq, Wk, bq, E, B);
    dot_kernel<<<(N + 7) / 8, 256>>>(x, seg, N);

    size_t smem_bytes =
        (size_t)(2 * TM * FDIM + KCHUNK * SW_STRIDE + TM) * sizeof(float);
    cudaFuncSetAttribute(chain_kernel,
                         cudaFuncAttributeMaxDynamicSharedMemorySize,
                         (int)smem_bytes);
    chain_kernel<<<(N + TM - 1) / TM, 256, smem_bytes>>>(
        seg, Wv, Wres1, Wres2, Wout, (float*)d_out, N);
}

// round 6
// speedup vs baseline: 1.4955x; 1.4955x over previous
#include <cuda_runtime.h>
#include <math.h>

// ---------------------------------------------------------------------------
// ElectronicEmbedding (SpookyNet) fused kernel set, R5.
//
// Algebra: q@Wk collapses (rank-1 k) -> dot_n = cf_b*(x_n.u + c0)/16
//          y is rank-1 per row: y[n,f] = s_n * Wv[f]
// Heavy part: 5 chained GEMMs [N,256]x[256,256] with silu, fused in one
// tile kernel (64 rows/CTA). R5: weight chunk held in registers (KCHUNK=8),
// vectorized broadcast A loads, double-buffered weight staging, FFMA2.
// ---------------------------------------------------------------------------

#define FDIM 256
#define TM 64
#define KCHUNK 8
#define NCHUNK (FDIM / KCHUNK)  // 32
#define SWS 264                 // padded smem row stride (floats), 16B-multiple
#define MAXN 200704
#define MAXB 4096

__device__ float g_u[FDIM];      // Wq^T @ Wk
__device__ float g_c0;           // bq . Wk
__device__ float g_cf[MAXB];     // |E|/max(|E|,1)
__device__ float g_ev[MAXB];     // |E|
__device__ float g_anorm[MAXB];  // segment sum of a
__device__ float g_a[MAXN];      // per-atom softplus attention weight
__device__ int   g_seg64;        // 1 if batch_seg is int64, 0 if int32

// -------- seg accessor: dtype decided at runtime, index always clamped -----
__device__ __forceinline__ int get_seg(const void* seg, int n) {
    int b;
    if (g_seg64) b = (int)((const long long*)seg)[n];
    else         b = ((const int*)seg)[n];
    if (b < 0) b = 0;
    if (b >= MAXB) b = MAXB - 1;
    return b;
}

// ---------------- packed f32x2 helpers (Blackwell FFMA2) -------------------
__device__ __forceinline__ unsigned long long packf2(float x, float y) {
    unsigned long long r;
    asm("mov.b64 %0, {%1, %2};" : "=l"(r)
        : "r"(__float_as_uint(x)), "r"(__float_as_uint(y)));
    return r;
}
__device__ __forceinline__ void unpackf2(unsigned long long v, float& x, float& y) {
    unsigned lo, hi;
    asm("mov.b64 {%0, %1}, %2;" : "=r"(lo), "=r"(hi) : "l"(v));
    x = __uint_as_float(lo);
    y = __uint_as_float(hi);
}
__device__ __forceinline__ void fma2(unsigned long long& d,
                                     unsigned long long a,
                                     unsigned long long b) {
    asm("fma.rn.f32x2 %0, %1, %2, %0;" : "+l"(d) : "l"(a), "l"(b));
}

__device__ __forceinline__ float siluf(float x) {
    return x * (1.0f / (1.0f + __expf(-x)));
}
__device__ __forceinline__ float4 silu4(float4 v) {
    return make_float4(siluf(v.x), siluf(v.y), siluf(v.z), siluf(v.w));
}

// ---------------------------------------------------------------------------
// Kernel 0: detect seg dtype. Reading int32[0..N-1] is safe for both dtypes.
// int64 LE: word N-1 is a high word = 0 while word N-2 > 0. int32: word N-1 > 0.
// ---------------------------------------------------------------------------
__global__ void detect_kernel(const int* __restrict__ seg32, int N) {
    int last = seg32[N - 1];
    int prev = seg32[N - 2];
    g_seg64 = (last == 0 && prev > 0) ? 1 : 0;
}

// ---------------------------------------------------------------------------
// Kernel A: prep. block 0 computes u, c0; other blocks per-batch factors.
// ---------------------------------------------------------------------------
__global__ void prep_kernel(const float* __restrict__ Wq,
                            const float* __restrict__ Wk,
                            const float* __restrict__ bq,
                            const float* __restrict__ E, int B) {
    int tid = threadIdx.x;
    if (blockIdx.x == 0) {
        float s = 0.0f;
#pragma unroll 8
        for (int f = 0; f < FDIM; f++)
            s = fmaf(Wk[f], Wq[f * FDIM + tid], s);
        g_u[tid] = s;
        if (tid == 0) {
            float c = 0.0f;
            for (int f = 0; f < FDIM; f++) c = fmaf(bq[f], Wk[f], c);
            g_c0 = c;
        }
    } else {
        int b = (blockIdx.x - 1) * 256 + tid;
        if (b < B) {
            float e = fabsf(E[b]);
            g_ev[b] = e;
            g_cf[b] = e / fmaxf(e, 1.0f);
            g_anorm[b] = 0.0f;
        }
    }
}

// ---------------------------------------------------------------------------
// Kernel B: per-atom dot (matvec) + softplus + atomic segment sum.
// ---------------------------------------------------------------------------
__global__ void dot_kernel(const float* __restrict__ x,
                           const void* __restrict__ seg, int N) {
    __shared__ float su[FDIM];
    __shared__ float sc0;
    int tid = threadIdx.x;
    su[tid] = g_u[tid];
    if (tid == 0) sc0 = g_c0;
    __syncthreads();

    int wid = tid >> 5, lane = tid & 31;
    int n = blockIdx.x * 8 + wid;
    if (n >= N) return;

    const float4* xr = (const float4*)(x + (size_t)n * FDIM);
    float4 xa = xr[lane];
    float4 xb = xr[32 + lane];
    float4 u0 = *(const float4*)&su[4 * lane];
    float4 u1 = *(const float4*)&su[128 + 4 * lane];
    float p = xa.x * u0.x + xa.y * u0.y + xa.z * u0.z + xa.w * u0.w +
              xb.x * u1.x + xb.y * u1.y + xb.z * u1.z + xb.w * u1.w;
#pragma unroll
    for (int o = 16; o > 0; o >>= 1) p += __shfl_down_sync(0xffffffffu, p, o);

    if (lane == 0) {
        int b = get_seg(seg, n);
        float d = (p + sc0) * g_cf[b] * 0.0625f;  // /sqrt(256)
        float a = fmaxf(d, 0.0f) + log1pf(expf(-fabsf(d)));
        g_a[n] = a;
        atomicAdd(&g_anorm[b], a);
    }
}

// ---------------------------------------------------------------------------
// GEMM tile: t[m][f] = sum_g A[m][g] * W[f][g], W row-major [F][F].
// KCHUNK=8 g's per chunk; weight chunk held in registers as f32x2 pairs;
// double-buffered staging (LDG chunk c+2 / STS chunk c+1 overlap compute c);
// one __syncthreads per chunk.
// ---------------------------------------------------------------------------
__device__ __forceinline__ void sts_chunk(float* __restrict__ dst, int tid,
                                          float4 r0, float4 r1) {
    float* d = dst + tid;  // lane-consecutive f -> conflict-free STS.32
    d[0 * SWS] = r0.x; d[1 * SWS] = r0.y; d[2 * SWS] = r0.z; d[3 * SWS] = r0.w;
    d[4 * SWS] = r1.x; d[5 * SWS] = r1.y; d[6 * SWS] = r1.z; d[7 * SWS] = r1.w;
}

__device__ __forceinline__ void gemm_tile(const float* __restrict__ gW,
                                          unsigned long long acc[8][4],
                                          const float* __restrict__ sA,
                                          float* __restrict__ sW,
                                          int tx, int ty, int tid) {
#pragma unroll
    for (int i = 0; i < 8; i++)
#pragma unroll
        for (int j = 0; j < 4; j++) acc[i][j] = 0ull;

    const float* aBase = sA + (ty * 8) * FDIM;
    // thread stages row f = tid; chunk c needs float4 indices c*2, c*2+1
    const float4* gRow = (const float4*)gW + (size_t)tid * (FDIM / 4);

    float4 r0 = gRow[0], r1 = gRow[1];
    sts_chunk(sW, tid, r0, r1);                 // chunk 0 -> buf 0
    r0 = gRow[2]; r1 = gRow[3];                 // prefetch chunk 1
    __syncthreads();                            // buf0 ready (+ publishes sA)

#pragma unroll 1
    for (int c = 0; c < NCHUNK; c++) {
        const float* buf = sW + (c & 1) * (KCHUNK * SWS);

        // weight chunk -> registers (16 LDS.128, pairs land pre-packed)
        ulonglong2 wlo[KCHUNK], whi[KCHUNK];
#pragma unroll
        for (int kk = 0; kk < KCHUNK; kk++) {
            wlo[kk] = *(const ulonglong2*)(buf + kk * SWS + 4 * tx);
            whi[kk] = *(const ulonglong2*)(buf + kk * SWS + 128 + 4 * tx);
        }

        const float* aChunk = aBase + c * KCHUNK;
#pragma unroll
        for (int i = 0; i < 8; i++) {
            float4 a0 = *(const float4*)(aChunk + i * FDIM);      // broadcast
            float4 a1 = *(const float4*)(aChunk + i * FDIM + 4);  // broadcast
            float av[KCHUNK] = {a0.x, a0.y, a0.z, a0.w, a1.x, a1.y, a1.z, a1.w};
#pragma unroll
            for (int kk = 0; kk < KCHUNK; kk++) {
                unsigned long long aa = packf2(av[kk], av[kk]);
                fma2(acc[i][0], aa, wlo[kk].x);
                fma2(acc[i][1], aa, wlo[kk].y);
                fma2(acc[i][2], aa, whi[kk].x);
                fma2(acc[i][3], aa, whi[kk].y);
            }
        }

        if (c + 1 < NCHUNK) {
            sts_chunk(sW + ((c + 1) & 1) * (KCHUNK * SWS), tid, r0, r1);
            if (c + 2 < NCHUNK) {
                r0 = gRow[(c + 2) * 2];
                r1 = gRow[(c + 2) * 2 + 1];
            }
        }
        __syncthreads();  // next buf published; current buf reads complete
    }
    // trailing barrier above: caller may immediately rewrite sA.
}

// ---------------------------------------------------------------------------
// Fused chain kernel: 64-row tile per CTA.
// Thread tile: 8 rows (ty*8..) x 8 cols (tx*4.. and 128+tx*4..).
// ---------------------------------------------------------------------------
__global__ __launch_bounds__(256, 1)
void chain_kernel(const void* __restrict__ seg,
                  const float* __restrict__ Wv,
                  const float* __restrict__ Wres1,
                  const float* __restrict__ Wres2,
                  const float* __restrict__ Wout,
                  float* __restrict__ out, int N) {
    extern __shared__ float sm[];
    float* sH = sm;                          // TM*FDIM
    float* sA = sH + TM * FDIM;              // TM*FDIM
    float* sW = sA + TM * FDIM;              // 2*KCHUNK*SWS (double buffer)
    float* sv = sW + 2 * KCHUNK * SWS;       // TM

    int tid = threadIdx.x;
    int tx = tid & 31, ty = tid >> 5;
    int r0 = blockIdx.x * TM;

    if (tid < TM) {
        int n = r0 + tid;
        float s = 0.0f;
        if (n < N) {
            int b = get_seg(seg, n);
            s = g_a[n] / (g_anorm[b] + 1e-8f) * g_ev[b];
        }
        sv[tid] = s;
    }
    __syncthreads();

    // h0[m,f] = s_m * Wv[f]; A = silu(h0)
    float4 wv0 = ((const float4*)Wv)[tx];
    float4 wv1 = ((const float4*)Wv)[32 + tx];
#pragma unroll
    for (int i = 0; i < 8; i++) {
        int r = ty * 8 + i;
        float s = sv[r];
        float4 h0 = make_float4(s * wv0.x, s * wv0.y, s * wv0.z, s * wv0.w);
        float4 h1 = make_float4(s * wv1.x, s * wv1.y, s * wv1.z, s * wv1.w);
        *(float4*)&sH[r * FDIM + tx * 4] = h0;
        *(float4*)&sH[r * FDIM + 128 + tx * 4] = h1;
        *(float4*)&sA[r * FDIM + tx * 4] = silu4(h0);
        *(float4*)&sA[r * FDIM + 128 + tx * 4] = silu4(h1);
    }
    // gemm_tile's prologue barrier publishes sA before first compute.

    unsigned long long acc[8][4];

#pragma unroll 1
    for (int it = 0; it < 2; it++) {
        // t = silu(h) @ Wres1[it].T
        gemm_tile(Wres1 + it * FDIM * FDIM, acc, sA, sW, tx, ty, tid);
        // A = silu(t)   (trailing barrier in gemm_tile makes this safe)
#pragma unroll
        for (int i = 0; i < 8; i++) {
            int r = ty * 8 + i;
            float4 v0, v1;
            unpackf2(acc[i][0], v0.x, v0.y);
            unpackf2(acc[i][1], v0.z, v0.w);
            unpackf2(acc[i][2], v1.x, v1.y);
            unpackf2(acc[i][3], v1.z, v1.w);
            *(float4*)&sA[r * FDIM + tx * 4] = silu4(v0);
            *(float4*)&sA[r * FDIM + 128 + tx * 4] = silu4(v1);
        }
        // h += A @ Wres2[it].T ; next A = silu(h)
        gemm_tile(Wres2 + it * FDIM * FDIM, acc, sA, sW, tx, ty, tid);
#pragma unroll
        for (int i = 0; i < 8; i++) {
            int r = ty * 8 + i;
            float4 d0, d1;
            unpackf2(acc[i][0], d0.x, d0.y);
            unpackf2(acc[i][1], d0.z, d0.w);
            unpackf2(acc[i][2], d1.x, d1.y);
            unpackf2(acc[i][3], d1.z, d1.w);
            float4 h0 = *(float4*)&sH[r * FDIM + tx * 4];
            float4 h1 = *(float4*)&sH[r * FDIM + 128 + tx * 4];
            h0.x += d0.x; h0.y += d0.y; h0.z += d0.z; h0.w += d0.w;
            h1.x += d1.x; h1.y += d1.y; h1.z += d1.z; h1.w += d1.w;
            *(float4*)&sH[r * FDIM + tx * 4] = h0;
            *(float4*)&sH[r * FDIM + 128 + tx * 4] = h1;
            *(float4*)&sA[r * FDIM + tx * 4] = silu4(h0);
            *(float4*)&sA[r * FDIM + 128 + tx * 4] = silu4(h1);
        }
    }

    // out = silu(h) @ Wout.T  (A already holds silu(h))
    gemm_tile(Wout, acc, sA, sW, tx, ty, tid);

#pragma unroll
    for (int i = 0; i < 8; i++) {
        int n = r0 + ty * 8 + i;
        if (n < N) {
            float4 o0, o1;
            unpackf2(acc[i][0], o0.x, o0.y);
            unpackf2(acc[i][1], o0.z, o0.w);
            unpackf2(acc[i][2], o1.x, o1.y);
            unpackf2(acc[i][3], o1.z, o1.w);
            *(float4*)&out[(size_t)n * FDIM + tx * 4] = o0;
            *(float4*)&out[(size_t)n * FDIM + 128 + tx * 4] = o1;
        }
    }
}

// ---------------------------------------------------------------------------
extern "C" void kernel_launch(void* const* d_in, const int* in_sizes, int n_in,
                              void* d_out, int out_size) {
    // Input order: x, E, [num_batch scalar], batch_seg, Wq, bq, Wk, Wv,
    // Wres1, Wres2, Wout. Scalar slot detected via in_sizes[2]==1.
    int base = (n_in >= 11 && in_sizes[2] == 1) ? 1 : 0;

    const float* x     = (const float*)d_in[0];
    const float* E     = (const float*)d_in[1];
    const void*  seg   = d_in[2 + base];
    const float* Wq    = (const float*)d_in[3 + base];
    const float* bq    = (const float*)d_in[4 + base];
    const float* Wk    = (const float*)d_in[5 + base];
    const float* Wv    = (const float*)d_in[6 + base];
    const float* Wres1 = (const float*)d_in[7 + base];
    const float* Wres2 = (const float*)d_in[8 + base];
    const float* Wout  = (const float*)d_in[9 + base];

    int N = in_sizes[0] / FDIM;
    int B = in_sizes[1];
    if (N > MAXN) N = MAXN;
    if (B > MAXB) B = MAXB;

    detect_kernel<<<1, 1>>>((const int*)seg, N);
    prep_kernel<<<1 + (B + 255) / 256, 256>>>(Wq, Wk, bq, E, B);
    dot_kernel<<<(N + 7) / 8, 256>>>(x, seg, N);

    size_t smem_bytes =
        (size_t)(2 * TM * FDIM + 2 * KCHUNK * SWS + TM) * sizeof(float);
    cudaFuncSetAttribute(chain_kernel,
                         cudaFuncAttributeMaxDynamicSharedMemorySize,
                         (int)smem_bytes);
    chain_kernel<<<(N + TM - 1) / TM, 256, smem_bytes>>>(
        seg, Wv, Wres1, Wres2, Wout, (float*)d_out, N);
}

// round 8
// speedup vs baseline: 2.7908x; 1.8661x over previous
#include <cuda_runtime.h>
#include <math.h>
#include <stdint.h>

// ===========================================================================
// ElectronicEmbedding (SpookyNet) — R8: bf16-split GEMM chain on HMMA
// (mma.sync.m16n8k16), since the harness targets base sm_103 (no tcgen05).
//
// dot_n = cf_b*(x_n.u + c0)/16 (rank-1 collapse);  y = s_n * Wv[f] (rank-1).
// Chain: h=y; 2x { h += silu(silu(h)@W1^T)@W2^T }; out = silu(h)@Wout^T.
// Each fp32 GEMM = 3 bf16 MMpéldául passes (Ah*Wh + Al*Wh + Ah*Wl).
// C-frag layout == A-frag layout (ntile pair -> ktile), so epilogues write
// A fragments directly; W pre-converted to fragment-ordered hi/lo chunks.
// ===========================================================================

#define FDIM 256
#define TM   64
#define MAXN 200704
#define MAXB 4096
#define CHUNK 32768   // one W chunk: 2 ktiles x 32 ntiles, hi+lo fragments

// W fragment images: [m 5][c 8] x 32KB = 1.31 MB (L2-resident)
__device__ __align__(16) unsigned char g_Wf[5 * 8 * CHUNK];

__device__ float g_u[FDIM];
__device__ float g_c0;
__device__ float g_cf[MAXB];
__device__ float g_ev[MAXB];
__device__ float g_anorm[MAXB];
__device__ float g_a[MAXN];
__device__ int   g_seg64;

// ---------------------------------------------------------------------------
__device__ __forceinline__ uint32_t smem_u32(const void* p) {
    uint32_t a;
    asm("{ .reg .u64 t; cvta.to.shared.u64 t, %1; cvt.u32.u64 %0, t; }"
        : "=r"(a) : "l"(p));
    return a;
}

__device__ __forceinline__ int get_seg(const void* seg, int n) {
    int b;
    if (g_seg64) b = (int)((const long long*)seg)[n];
    else         b = ((const int*)seg)[n];
    if (b < 0) b = 0;
    if (b >= MAXB) b = MAXB - 1;
    return b;
}

__device__ __forceinline__ float siluf(float x) {
    return x * (1.0f / (1.0f + __expf(-x)));
}

// split two floats into packed bf16x2 hi word + lo (residual) word.
// word layout: low half = a, high half = b.
__device__ __forceinline__ void bf16split2(float a, float b,
                                           uint32_t& hp, uint32_t& lp) {
    uint32_t h;
    asm("cvt.rn.satfinite.bf16x2.f32 %0, %1, %2;" : "=r"(h) : "f"(b), "f"(a));
    float ha = __uint_as_float(h << 16);
    float hb = __uint_as_float(h & 0xffff0000u);
    uint32_t l;
    asm("cvt.rn.satfinite.bf16x2.f32 %0, %1, %2;" : "=r"(l)
        : "f"(b - hb), "f"(a - ha));
    hp = h; lp = l;
}
__device__ __forceinline__ float lo16f(uint32_t w) { return __uint_as_float(w << 16); }
__device__ __forceinline__ float hi16f(uint32_t w) { return __uint_as_float(w & 0xffff0000u); }

// ---------------------------------------------------------------------------
// mbarrier / bulk copy (plain sm_90-class PTX, compiles on sm_103 base)
// ---------------------------------------------------------------------------
__device__ __forceinline__ void mbar_init(uint32_t m, uint32_t cnt) {
    asm volatile("mbarrier.init.shared.b64 [%0], %1;" :: "r"(m), "r"(cnt) : "memory");
}
__device__ __forceinline__ void mbar_expect(uint32_t m, uint32_t bytes) {
    asm volatile("mbarrier.arrive.expect_tx.shared.b64 _, [%0], %1;"
                 :: "r"(m), "r"(bytes) : "memory");
}
__device__ __forceinline__ void mbar_wait(uint32_t m, uint32_t parity) {
    uint32_t done;
    asm volatile(
        "{\n\t.reg .pred p;\n\t"
        "mbarrier.try_wait.parity.acquire.cta.shared::cta.b64 p, [%1], %2;\n\t"
        "selp.b32 %0, 1, 0, p;\n\t}"
        : "=r"(done) : "r"(m), "r"(parity) : "memory");
    while (!done) {
        asm volatile(
            "{\n\t.reg .pred p;\n\t"
            "mbarrier.try_wait.parity.acquire.cta.shared::cta.b64 p, [%1], %2, 0x989680;\n\t"
            "selp.b32 %0, 1, 0, p;\n\t}"
            : "=r"(done) : "r"(m), "r"(parity) : "memory");
    }
}
__device__ __forceinline__ void bulk_g2s(uint32_t dst, const void* src,
                                         uint32_t bytes, uint32_t mbar) {
    asm volatile(
        "cp.async.bulk.shared::cluster.global.mbarrier::complete_tx::bytes "
        "[%0], [%1], %2, [%3];"
        :: "r"(dst), "l"(src), "r"(bytes), "r"(mbar) : "memory");
}
#define FENCE_ASYNC() asm volatile("fence.proxy.async.shared::cta;" ::: "memory")

// m16n8k16 bf16 MMA, f32 accumulate
__device__ __forceinline__ void mma16816(float c[4], uint32_t a0, uint32_t a1,
                                         uint32_t a2, uint32_t a3,
                                         uint32_t b0, uint32_t b1) {
    asm volatile(
        "mma.sync.aligned.m16n8k16.row.col.f32.bf16.bf16.f32 "
        "{%0,%1,%2,%3}, {%4,%5,%6,%7}, {%8,%9}, {%0,%1,%2,%3};"
        : "+f"(c[0]), "+f"(c[1]), "+f"(c[2]), "+f"(c[3])
        : "r"(a0), "r"(a1), "r"(a2), "r"(a3), "r"(b0), "r"(b1));
}

// ---------------------------------------------------------------------------
// detect / prep / dot (passing since R5)
// ---------------------------------------------------------------------------
__global__ void detect_kernel(const int* __restrict__ seg32, int N) {
    int last = seg32[N - 1];
    int prev = seg32[N - 2];
    g_seg64 = (last == 0 && prev > 0) ? 1 : 0;
}

__global__ void prep_kernel(const float* __restrict__ Wq,
                            const float* __restrict__ Wk,
                            const float* __restrict__ bq,
                            const float* __restrict__ E, int B) {
    int tid = threadIdx.x;
    if (blockIdx.x == 0) {
        float s = 0.0f;
#pragma unroll 8
        for (int f = 0; f < FDIM; f++)
            s = fmaf(Wk[f], Wq[f * FDIM + tid], s);
        g_u[tid] = s;
        if (tid == 0) {
            float c = 0.0f;
            for (int f = 0; f < FDIM; f++) c = fmaf(bq[f], Wk[f], c);
            g_c0 = c;
        }
    } else {
        int b = (blockIdx.x - 1) * 256 + tid;
        if (b < B) {
            float e = fabsf(E[b]);
            g_ev[b] = e;
            g_cf[b] = e / fmaxf(e, 1.0f);
            g_anorm[b] = 0.0f;
        }
    }
}

__global__ void dot_kernel(const float* __restrict__ x,
                           const void* __restrict__ seg, int N) {
    __shared__ float su[FDIM];
    __shared__ float sc0;
    int tid = threadIdx.x;
    su[tid] = g_u[tid];
    if (tid == 0) sc0 = g_c0;
    __syncthreads();

    int wid = tid >> 5, lane = tid & 31;
    int n = blockIdx.x * 8 + wid;
    if (n >= N) return;

    const float4* xr = (const float4*)(x + (size_t)n * FDIM);
    float4 xa = xr[lane];
    float4 xb = xr[32 + lane];
    float4 u0 = *(const float4*)&su[4 * lane];
    float4 u1 = *(const float4*)&su[128 + 4 * lane];
    float p = xa.x * u0.x + xa.y * u0.y + xa.z * u0.z + xa.w * u0.w +
              xb.x * u1.x + xb.y * u1.y + xb.z * u1.z + xb.w * u1.w;
#pragma unroll
    for (int o = 16; o > 0; o >>= 1) p += __shfl_down_sync(0xffffffffu, p, o);

    if (lane == 0) {
        int b = get_seg(seg, n);
        float d = (p + sc0) * g_cf[b] * 0.0625f;
        float a = fmaxf(d, 0.0f) + log1pf(expf(-fabsf(d)));
        g_a[n] = a;
        atomicAdd(&g_anorm[b], a);
    }
}

// ---------------------------------------------------------------------------
// convW: fp32 W[out][in] -> fragment-ordered bf16 hi/lo chunk images.
// chunk layout: [s(2)][t2(2)][j(32)][l(32)][2 uint32]; chunks: [m(5)][c(8)].
// B frag: b0={B[k0][n],B[k0+1][n]}, b1={B[k0+8][n],B[k0+9][n]},
// n=8j+(l>>2), k0=32c+16t2+(l&3)*2, B[k][n] = W[n][k].
// ---------------------------------------------------------------------------
__global__ void convW_kernel(const float* __restrict__ Wres1,
                             const float* __restrict__ Wres2,
                             const float* __restrict__ Wout) {
    int idx = blockIdx.x * blockDim.x + threadIdx.x;
    if (idx >= 5 * 8 * 2 * 32 * 32) return;   // 81920
    int l  = idx & 31;
    int j  = (idx >> 5) & 31;
    int t2 = (idx >> 10) & 1;
    int c  = (idx >> 11) & 7;
    int m  = idx >> 14;

    const float* Wm;
    switch (m) {
        case 0: Wm = Wres1; break;
        case 1: Wm = Wres2; break;
        case 2: Wm = Wres1 + 65536; break;
        case 3: Wm = Wres2 + 65536; break;
        default: Wm = Wout; break;
    }
    int n  = 8 * j + (l >> 2);
    int k0 = 32 * c + 16 * t2 + (l & 3) * 2;
    const float* p = Wm + n * FDIM + k0;
    float v0 = p[0], v1 = p[1], v2 = p[8], v3 = p[9];
    uint32_t H0, L0, H1, L1;
    bf16split2(v0, v1, H0, L0);
    bf16split2(v2, v3, H1, L1);
    size_t base = (size_t)(m * 8 + c) * CHUNK +
                  (size_t)(((t2 * 32 + j) * 32 + l)) * 8;
    *(uint2*)(g_Wf + base)         = make_uint2(H0, H1);   // s=0 (hi)
    *(uint2*)(g_Wf + base + 16384) = make_uint2(L0, L1);   // s=1 (lo)
}

// ---------------------------------------------------------------------------
// chain_mma: 64 rows/CTA, 128 threads (4 warps x 16 rows).
// SMEM: aH 32K | aL 32K | hH 32K | hL 32K | wbuf0 32K | wbuf1 32K = 192K.
// ---------------------------------------------------------------------------
__global__ __launch_bounds__(128, 1)
void chain_mma(const void* __restrict__ seg,
               const float* __restrict__ Wv,
               float* __restrict__ out, int N) {
    extern __shared__ __align__(1024) unsigned char dyn[];
    unsigned char* aH = dyn;
    unsigned char* aL = dyn + 32768;
    unsigned char* hH = dyn + 65536;
    unsigned char* hL = dyn + 98304;
    uint32_t wb_addr[2] = { smem_u32(dyn + 131072), smem_u32(dyn + 163840) };
    unsigned char* wb_ptr[2] = { dyn + 131072, dyn + 163840 };

    __shared__ __align__(8) unsigned long long s_mb[2];
    __shared__ float s_sv[TM];
    __shared__ float s_wv[FDIM];

    int tid = threadIdx.x;
    int w = tid >> 5, l = tid & 31;
    int gid = l >> 2;             // row group 0..7
    int c2v = (l & 3) * 2;        // col-in-tile offset
    int r0 = blockIdx.x * TM;

    uint32_t mb[2] = { smem_u32(&s_mb[0]), smem_u32(&s_mb[1]) };

    if (tid == 0) {
        mbar_init(mb[0], 1);
        mbar_init(mb[1], 1);
        FENCE_ASYNC();
    }
    if (tid < TM) {
        int n = r0 + tid;
        float s = 0.0f;
        if (n < N) {
            int b = get_seg(seg, n);
            s = g_a[n] / (g_anorm[b] + 1e-8f) * g_ev[b];
        }
        s_sv[tid] = s;
    }
    s_wv[tid] = Wv[tid];
    s_wv[tid + 128] = Wv[tid + 128];
    __syncthreads();

    if (tid == 0) {
        mbar_expect(mb[0], CHUNK);
        bulk_g2s(wb_addr[0], g_Wf, CHUNK, mb[0]);
        mbar_expect(mb[1], CHUNK);
        bulk_g2s(wb_addr[1], g_Wf + CHUNK, CHUNK, mb[1]);
    }

    // ---- init: h0 = s (x) Wv; store h hi/lo (C-layout) and A=silu(h0) frags
    {
        float s0 = s_sv[16 * w + gid];
        float s1 = s_sv[16 * w + gid + 8];
#pragma unroll
        for (int t = 0; t < 16; t++) {
            float w0 = s_wv[16 * t + c2v],     w1 = s_wv[16 * t + c2v + 1];
            float w2 = s_wv[16 * t + 8 + c2v], w3 = s_wv[16 * t + 8 + c2v + 1];
            float x0 = s0 * w0, x1 = s0 * w1, x2 = s1 * w0, x3 = s1 * w1;  // j=2t
            float y0 = s0 * w2, y1 = s0 * w3, y2 = s1 * w2, y3 = s1 * w3;  // j=2t+1
            uint32_t H0, L0, H1, L1, H2, L2, H3, L3;
            bf16split2(siluf(x0), siluf(x1), H0, L0);
            bf16split2(siluf(x2), siluf(x3), H1, L1);
            bf16split2(siluf(y0), siluf(y1), H2, L2);
            bf16split2(siluf(y2), siluf(y3), H3, L3);
            size_t ao = (size_t)((w * 16 + t) * 32 + l) * 16;
            *(uint4*)(aH + ao) = make_uint4(H0, H1, H2, H3);
            *(uint4*)(aL + ao) = make_uint4(L0, L1, L2, L3);
            uint32_t hh0, hl0, hh1, hl1;
            bf16split2(x0, x1, hh0, hl0);
            bf16split2(x2, x3, hh1, hl1);
            size_t ho = (size_t)((w * 32 + 2 * t) * 32 + l) * 8;
            *(uint2*)(hH + ho) = make_uint2(hh0, hh1);
            *(uint2*)(hL + ho) = make_uint2(hl0, hl1);
            bf16split2(y0, y1, hh0, hl0);
            bf16split2(y2, y3, hh1, hl1);
            *(uint2*)(hH + ho + 256) = make_uint2(hh0, hh1);
            *(uint2*)(hL + ho + 256) = make_uint2(hl0, hl1);
        }
    }
    __syncthreads();

    float C[32][4];

#pragma unroll 1
    for (int g = 0; g < 5; g++) {
        // ---- accumulator init: residual GEMMs start from h
        if (g == 1 || g == 3) {
#pragma unroll
            for (int j = 0; j < 32; j++) {
                size_t ho = (size_t)((w * 32 + j) * 32 + l) * 8;
                uint2 H = *(uint2*)(hH + ho);
                uint2 L = *(uint2*)(hL + ho);
                C[j][0] = lo16f(H.x) + lo16f(L.x);
                C[j][1] = hi16f(H.x) + hi16f(L.x);
                C[j][2] = lo16f(H.y) + lo16f(L.y);
                C[j][3] = hi16f(H.y) + hi16f(L.y);
            }
        } else {
#pragma unroll
            for (int j = 0; j < 32; j++)
                C[j][0] = C[j][1] = C[j][2] = C[j][3] = 0.0f;
        }

        // ---- mainloop: 8 k-chunks of 32
#pragma unroll 1
        for (int c = 0; c < 8; c++) {
            int q = 8 * g + c;
            mbar_wait(mb[q & 1], (uint32_t)((q >> 1) & 1));
            const unsigned char* wb = wb_ptr[q & 1];

            size_t ao = (size_t)((w * 16 + 2 * c) * 32 + l) * 16;
            uint4 ah0 = *(const uint4*)(aH + ao);
            uint4 ah1 = *(const uint4*)(aH + ao + 512);
            uint4 al0 = *(const uint4*)(aL + ao);
            uint4 al1 = *(const uint4*)(aL + ao + 512);
            const unsigned char* wt = wb + (size_t)l * 8;

#pragma unroll
            for (int j = 0; j < 32; j++) {
                uint2 bh0 = *(const uint2*)(wt + j * 256);
                mma16816(C[j], ah0.x, ah0.y, ah0.z, ah0.w, bh0.x, bh0.y);
                mma16816(C[j], al0.x, al0.y, al0.z, al0.w, bh0.x, bh0.y);
                uint2 bl0 = *(const uint2*)(wt + 16384 + j * 256);
                mma16816(C[j], ah0.x, ah0.y, ah0.z, ah0.w, bl0.x, bl0.y);
                uint2 bh1 = *(const uint2*)(wt + 8192 + j * 256);
                mma16816(C[j], ah1.x, ah1.y, ah1.z, ah1.w, bh1.x, bh1.y);
                mma16816(C[j], al1.x, al1.y, al1.z, al1.w, bh1.x, bh1.y);
                uint2 bl1 = *(const uint2*)(wt + 24576 + j * 256);
                mma16816(C[j], ah1.x, ah1.y, ah1.z, ah1.w, bl1.x, bl1.y);
            }
            __syncthreads();   // all warps done with this buffer
            if (tid == 0 && q + 2 < 40) {
                int qq = q + 2;
                mbar_expect(mb[qq & 1], CHUNK);
                bulk_g2s(wb_addr[qq & 1], g_Wf + (size_t)qq * CHUNK, CHUNK,
                         mb[qq & 1]);
            }
        }

        // ---- epilogue
        if (g == 4) {
            int n0 = r0 + 16 * w + gid;
            int n1 = n0 + 8;
            if (n0 < N) {
                float* o = out + (size_t)n0 * FDIM + c2v;
#pragma unroll
                for (int j = 0; j < 32; j++)
                    *(float2*)(o + 8 * j) = make_float2(C[j][0], C[j][1]);
            }
            if (n1 < N) {
                float* o = out + (size_t)n1 * FDIM + c2v;
#pragma unroll
                for (int j = 0; j < 32; j++)
                    *(float2*)(o + 8 * j) = make_float2(C[j][2], C[j][3]);
            }
        } else {
            bool storeH = (g == 1 || g == 3);
#pragma unroll
            for (int t = 0; t < 16; t++) {
                float x0 = C[2 * t][0], x1 = C[2 * t][1];
                float x2 = C[2 * t][2], x3 = C[2 * t][3];
                float y0 = C[2 * t + 1][0], y1 = C[2 * t + 1][1];
                float y2 = C[2 * t + 1][2], y3 = C[2 * t + 1][3];
                uint32_t H0, L0, H1, L1, H2, L2, H3, L3;
                bf16split2(siluf(x0), siluf(x1), H0, L0);
                bf16split2(siluf(x2), siluf(x3), H1, L1);
                bf16split2(siluf(y0), siluf(y1), H2, L2);
                bf16split2(siluf(y2), siluf(y3), H3, L3);
                size_t ao = (size_t)((w * 16 + t) * 32 + l) * 16;
                *(uint4*)(aH + ao) = make_uint4(H0, H1, H2, H3);
                *(uint4*)(aL + ao) = make_uint4(L0, L1, L2, L3);
                if (storeH) {
                    uint32_t hh0, hl0, hh1, hl1;
                    bf16split2(x0, x1, hh0, hl0);
                    bf16split2(x2, x3, hh1, hl1);
                    size_t ho = (size_t)((w * 32 + 2 * t) * 32 + l) * 8;
                    *(uint2*)(hH + ho) = make_uint2(hh0, hh1);
                    *(uint2*)(hL + ho) = make_uint2(hl0, hl1);
                    bf16split2(y0, y1, hh0, hl0);
                    bf16split2(y2, y3, hh1, hl1);
                    *(uint2*)(hH + ho + 256) = make_uint2(hh0, hh1);
                    *(uint2*)(hL + ho + 256) = make_uint2(hl0, hl1);
                }
            }
            __syncthreads();   // publish A (and h) before next GEMM
        }
    }
}

// ---------------------------------------------------------------------------
extern "C" void kernel_launch(void* const* d_in, const int* in_sizes, int n_in,
                              void* d_out, int out_size) {
    int base = (n_in >= 11 && in_sizes[2] == 1) ? 1 : 0;

    const float* x     = (const float*)d_in[0];
    const float* E     = (const float*)d_in[1];
    const void*  seg   = d_in[2 + base];
    const float* Wq    = (const float*)d_in[3 + base];
    const float* bq    = (const float*)d_in[4 + base];
    const float* Wk    = (const float*)d_in[5 + base];
    const float* Wv    = (const float*)d_in[6 + base];
    const float* Wres1 = (const float*)d_in[7 + base];
    const float* Wres2 = (const float*)d_in[8 + base];
    const float* Wout  = (const float*)d_in[9 + base];

    int N = in_sizes[0] / FDIM;
    int B = in_sizes[1];
    if (N > MAXN) N = MAXN;
    if (B > MAXB) B = MAXB;

    detect_kernel<<<1, 1>>>((const int*)seg, N);
    prep_kernel<<<1 + (B + 255) / 256, 256>>>(Wq, Wk, bq, E, B);
    convW_kernel<<<(81920 + 127) / 128, 128>>>(Wres1, Wres2, Wout);
    dot_kernel<<<(N + 7) / 8, 256>>>(x, seg, N);

    int smem_bytes = 196608;
    cudaFuncSetAttribute(chain_mma, cudaFuncAttributeMaxDynamicSharedMemorySize,
                         smem_bytes);
    chain_mma<<<(N + TM - 1) / TM, 128, smem_bytes>>>(seg, Wv, (float*)d_out, N);
}

// round 9
// speedup vs baseline: 3.1006x; 1.1110x over previous
#include <cuda_runtime.h>
#include <math.h>
#include <stdint.h>

// ===========================================================================
// ElectronicEmbedding (SpookyNet) — R9: bf16-split HMMA chain, 8-warp n-split.
//
// dot_n = cf_b*(x_n.u + c0)/16 (rank-1 collapse);  y = s_n * Wv[f] (rank-1).
// Chain: h=y; 2x { h += silu(silu(h)@W1^T)@W2^T }; out = silu(h)@Wout^T.
// Each fp32 GEMM = 3 bf16 MMA passes (Ah*Wh + Al*Wh + Ah*Wl).
// 64 rows/CTA, 256 threads: warp (m = w&3, nh = w>>2) owns 16 rows x 128 cols.
// h kept fp32 in fragment-ordered SMEM (warp-private). 4-way MMA interleave.
// ===========================================================================

#define FDIM 256
#define TM   64
#define MAXN 200704
#define MAXB 4096
#define CHUNK 32768   // one W chunk: 2 ktiles x 32 ntiles, hi+lo fragments

__device__ __align__(16) unsigned char g_Wf[5 * 8 * CHUNK];

__device__ float g_u[FDIM];
__device__ float g_c0;
__device__ float g_cf[MAXB];
__device__ float g_ev[MAXB];
__device__ float g_anorm[MAXB];
__device__ float g_a[MAXN];
__device__ int   g_seg64;

// ---------------------------------------------------------------------------
__device__ __forceinline__ uint32_t smem_u32(const void* p) {
    uint32_t a;
    asm("{ .reg .u64 t; cvta.to.shared.u64 t, %1; cvt.u32.u64 %0, t; }"
        : "=r"(a) : "l"(p));
    return a;
}

__device__ __forceinline__ int get_seg(const void* seg, int n) {
    int b;
    if (g_seg64) b = (int)((const long long*)seg)[n];
    else         b = ((const int*)seg)[n];
    if (b < 0) b = 0;
    if (b >= MAXB) b = MAXB - 1;
    return b;
}

__device__ __forceinline__ float siluf(float x) {
    return x * (1.0f / (1.0f + __expf(-x)));
}

// split two floats into packed bf16x2 hi word + lo (residual) word.
__device__ __forceinline__ void bf16split2(float a, float b,
                                           uint32_t& hp, uint32_t& lp) {
    uint32_t h;
    asm("cvt.rn.satfinite.bf16x2.f32 %0, %1, %2;" : "=r"(h) : "f"(b), "f"(a));
    float ha = __uint_as_float(h << 16);
    float hb = __uint_as_float(h & 0xffff0000u);
    uint32_t l;
    asm("cvt.rn.satfinite.bf16x2.f32 %0, %1, %2;" : "=r"(l)
        : "f"(b - hb), "f"(a - ha));
    hp = h; lp = l;
}

// ---------------------------------------------------------------------------
// mbarrier / bulk copy (sm_90-class PTX, fine on base sm_103)
// ---------------------------------------------------------------------------
__device__ __forceinline__ void mbar_init(uint32_t m, uint32_t cnt) {
    asm volatile("mbarrier.init.shared.b64 [%0], %1;" :: "r"(m), "r"(cnt) : "memory");
}
__device__ __forceinline__ void mbar_expect(uint32_t m, uint32_t bytes) {
    asm volatile("mbarrier.arrive.expect_tx.shared.b64 _, [%0], %1;"
                 :: "r"(m), "r"(bytes) : "memory");
}
__device__ __forceinline__ void mbar_wait(uint32_t m, uint32_t parity) {
    uint32_t done;
    asm volatile(
        "{\n\t.reg .pred p;\n\t"
        "mbarrier.try_wait.parity.acquire.cta.shared::cta.b64 p, [%1], %2;\n\t"
        "selp.b32 %0, 1, 0, p;\n\t}"
        : "=r"(done) : "r"(m), "r"(parity) : "memory");
    while (!done) {
        asm volatile(
            "{\n\t.reg .pred p;\n\t"
            "mbarrier.try_wait.parity.acquire.cta.shared::cta.b64 p, [%1], %2, 0x989680;\n\t"
            "selp.b32 %0, 1, 0, p;\n\t}"
            : "=r"(done) : "r"(m), "r"(parity) : "memory");
    }
}
__device__ __forceinline__ void bulk_g2s(uint32_t dst, const void* src,
                                         uint32_t bytes, uint32_t mbar) {
    asm volatile(
        "cp.async.bulk.shared::cluster.global.mbarrier::complete_tx::bytes "
        "[%0], [%1], %2, [%3];"
        :: "r"(dst), "l"(src), "r"(bytes), "r"(mbar) : "memory");
}
#define FENCE_ASYNC() asm volatile("fence.proxy.async.shared::cta;" ::: "memory")

__device__ __forceinline__ void mma16816(float c[4], uint32_t a0, uint32_t a1,
                                         uint32_t a2, uint32_t a3,
                                         uint32_t b0, uint32_t b1) {
    asm volatile(
        "mma.sync.aligned.m16n8k16.row.col.f32.bf16.bf16.f32 "
        "{%0,%1,%2,%3}, {%4,%5,%6,%7}, {%8,%9}, {%0,%1,%2,%3};"
        : "+f"(c[0]), "+f"(c[1]), "+f"(c[2]), "+f"(c[3])
        : "r"(a0), "r"(a1), "r"(a2), "r"(a3), "r"(b0), "r"(b1));
}

// ---------------------------------------------------------------------------
// detect / prep / dot (passing since R5)
// ---------------------------------------------------------------------------
__global__ void detect_kernel(const int* __restrict__ seg32, int N) {
    int last = seg32[N - 1];
    int prev = seg32[N - 2];
    g_seg64 = (last == 0 && prev > 0) ? 1 : 0;
}

__global__ void prep_kernel(const float* __restrict__ Wq,
                            const float* __restrict__ Wk,
                            const float* __restrict__ bq,
                            const float* __restrict__ E, int B) {
    int tid = threadIdx.x;
    if (blockIdx.x == 0) {
        float s = 0.0f;
#pragma unroll 8
        for (int f = 0; f < FDIM; f++)
            s = fmaf(Wk[f], Wq[f * FDIM + tid], s);
        g_u[tid] = s;
        if (tid == 0) {
            float c = 0.0f;
            for (int f = 0; f < FDIM; f++) c = fmaf(bq[f], Wk[f], c);
            g_c0 = c;
        }
    } else {
        int b = (blockIdx.x - 1) * 256 + tid;
        if (b < B) {
            float e = fabsf(E[b]);
            g_ev[b] = e;
            g_cf[b] = e / fmaxf(e, 1.0f);
            g_anorm[b] = 0.0f;
        }
    }
}

__global__ void dot_kernel(const float* __restrict__ x,
                           const void* __restrict__ seg, int N) {
    __shared__ float su[FDIM];
    __shared__ float sc0;
    int tid = threadIdx.x;
    su[tid] = g_u[tid];
    if (tid == 0) sc0 = g_c0;
    __syncthreads();

    int wid = tid >> 5, lane = tid & 31;
    int n = blockIdx.x * 8 + wid;
    if (n >= N) return;

    const float4* xr = (const float4*)(x + (size_t)n * FDIM);
    float4 xa = xr[lane];
    float4 xb = xr[32 + lane];
    float4 u0 = *(const float4*)&su[4 * lane];
    float4 u1 = *(const float4*)&su[128 + 4 * lane];
    float p = xa.x * u0.x + xa.y * u0.y + xa.z * u0.z + xa.w * u0.w +
              xb.x * u1.x + xb.y * u1.y + xb.z * u1.z + xb.w * u1.w;
#pragma unroll
    for (int o = 16; o > 0; o >>= 1) p += __shfl_down_sync(0xffffffffu, p, o);

    if (lane == 0) {
        int b = get_seg(seg, n);
        float d = (p + sc0) * g_cf[b] * 0.0625f;
        float a = fmaxf(d, 0.0f) + log1pf(expf(-fabsf(d)));
        g_a[n] = a;
        atomicAdd(&g_anorm[b], a);
    }
}

// ---------------------------------------------------------------------------
// convW: fp32 W[out][in] -> fragment-ordered bf16 hi/lo chunk images.
// chunk layout: [s(2)][t2(2)][j(32)][l(32)][2 uint32]; chunks: [m(5)][c(8)].
// ---------------------------------------------------------------------------
__global__ void convW_kernel(const float* __restrict__ Wres1,
                             const float* __restrict__ Wres2,
                             const float* __restrict__ Wout) {
    int idx = blockIdx.x * blockDim.x + threadIdx.x;
    if (idx >= 5 * 8 * 2 * 32 * 32) return;   // 81920
    int l  = idx & 31;
    int j  = (idx >> 5) & 31;
    int t2 = (idx >> 10) & 1;
    int c  = (idx >> 11) & 7;
    int m  = idx >> 14;

    const float* Wm;
    switch (m) {
        case 0: Wm = Wres1; break;
        case 1: Wm = Wres2; break;
        case 2: Wm = Wres1 + 65536; break;
        case 3: Wm = Wres2 + 65536; break;
        default: Wm = Wout; break;
    }
    int n  = 8 * j + (l >> 2);
    int k0 = 32 * c + 16 * t2 + (l & 3) * 2;
    const float* p = Wm + n * FDIM + k0;
    float v0 = p[0], v1 = p[1], v2 = p[8], v3 = p[9];
    uint32_t H0, L0, H1, L1;
    bf16split2(v0, v1, H0, L0);
    bf16split2(v2, v3, H1, L1);
    size_t base = (size_t)(m * 8 + c) * CHUNK +
                  (size_t)(((t2 * 32 + j) * 32 + l)) * 8;
    *(uint2*)(g_Wf + base)         = make_uint2(H0, H1);   // hi
    *(uint2*)(g_Wf + base + 16384) = make_uint2(L0, L1);   // lo
}

// ---------------------------------------------------------------------------
// chain_mma: 64 rows/CTA, 256 threads (8 warps). warp = (m = w&3, nh = w>>2).
// SMEM: aH 32K | aL 32K | hF 64K | wbuf0 32K | wbuf1 32K = 192K.
// ---------------------------------------------------------------------------
__global__ __launch_bounds__(256, 1)
void chain_mma(const void* __restrict__ seg,
               const float* __restrict__ Wv,
               float* __restrict__ out, int N) {
    extern __shared__ __align__(1024) unsigned char dyn[];
    unsigned char* aH = dyn;
    unsigned char* aL = dyn + 32768;
    unsigned char* hF = dyn + 65536;
    uint32_t wb_addr[2] = { smem_u32(dyn + 131072), smem_u32(dyn + 163840) };
    unsigned char* wb_ptr[2] = { dyn + 131072, dyn + 163840 };

    __shared__ __align__(8) unsigned long long s_mb[2];
    __shared__ float s_sv[TM];
    __shared__ float s_wv[FDIM];

    int tid = threadIdx.x;
    int w = tid >> 5, l = tid & 31;
    int m = w & 3, nh = w >> 2;
    int gid = l >> 2;
    int c2v = (l & 3) * 2;
    int r0 = blockIdx.x * TM;

    uint32_t mb[2] = { smem_u32(&s_mb[0]), smem_u32(&s_mb[1]) };

    if (tid == 0) {
        mbar_init(mb[0], 1);
        mbar_init(mb[1], 1);
        FENCE_ASYNC();
    }
    if (tid < TM) {
        int n = r0 + tid;
        float s = 0.0f;
        if (n < N) {
            int b = get_seg(seg, n);
            s = g_a[n] / (g_anorm[b] + 1e-8f) * g_ev[b];
        }
        s_sv[tid] = s;
    }
    s_wv[tid] = Wv[tid];
    __syncthreads();

    if (tid == 0) {
        mbar_expect(mb[0], CHUNK);
        bulk_g2s(wb_addr[0], g_Wf, CHUNK, mb[0]);
        mbar_expect(mb[1], CHUNK);
        bulk_g2s(wb_addr[1], g_Wf + CHUNK, CHUNK, mb[1]);
    }

    // ---- init: h0 = s (x) Wv; A = bf16split(silu(h0)), h fp32 frag-order.
    {
        float s0 = s_sv[16 * m + gid];
        float s1 = s_sv[16 * m + gid + 8];
#pragma unroll
        for (int t = 0; t < 8; t++) {
            int j0 = 2 * t, j1 = 2 * t + 1;
            float w00 = s_wv[128 * nh + 8 * j0 + c2v];
            float w01 = s_wv[128 * nh + 8 * j0 + c2v + 1];
            float w10 = s_wv[128 * nh + 8 * j1 + c2v];
            float w11 = s_wv[128 * nh + 8 * j1 + c2v + 1];
            float x0 = s0 * w00, x1 = s0 * w01, x2 = s1 * w00, x3 = s1 * w01;
            float y0 = s0 * w10, y1 = s0 * w11, y2 = s1 * w10, y3 = s1 * w11;
            uint32_t H0, L0, H1, L1, H2, L2, H3, L3;
            bf16split2(siluf(x0), siluf(x1), H0, L0);
            bf16split2(siluf(x2), siluf(x3), H1, L1);
            bf16split2(siluf(y0), siluf(y1), H2, L2);
            bf16split2(siluf(y2), siluf(y3), H3, L3);
            size_t ao = (size_t)((m * 16 + 8 * nh + t) * 32 + l) * 16;
            *(uint4*)(aH + ao) = make_uint4(H0, H1, H2, H3);
            *(uint4*)(aL + ao) = make_uint4(L0, L1, L2, L3);
            size_t ho = (size_t)((w * 16 + j0) * 32 + l) * 16;
            *(float4*)(hF + ho) = make_float4(x0, x1, x2, x3);
            *(float4*)(hF + ho + 512) = make_float4(y0, y1, y2, y3);
        }
    }
    __syncthreads();

    float C[16][4];

#pragma unroll 1
    for (int g = 0; g < 5; g++) {
        // ---- accumulator init
        if (g == 1 || g == 3) {
#pragma unroll
            for (int j = 0; j < 16; j++) {
                float4 hv = *(float4*)(hF + (size_t)((w * 16 + j) * 32 + l) * 16);
                C[j][0] = hv.x; C[j][1] = hv.y; C[j][2] = hv.z; C[j][3] = hv.w;
            }
        } else {
#pragma unroll
            for (int j = 0; j < 16; j++)
                C[j][0] = C[j][1] = C[j][2] = C[j][3] = 0.0f;
        }

        // ---- mainloop: 8 k-chunks of 32
#pragma unroll 1
        for (int c = 0; c < 8; c++) {
            int q = 8 * g + c;
            mbar_wait(mb[q & 1], (uint32_t)((q >> 1) & 1));
            const unsigned char* wb = wb_ptr[q & 1];

            size_t ao = (size_t)((m * 16 + 2 * c) * 32 + l) * 16;
            uint4 ah0 = *(const uint4*)(aH + ao);
            uint4 ah1 = *(const uint4*)(aH + ao + 512);
            uint4 al0 = *(const uint4*)(aL + ao);
            uint4 al1 = *(const uint4*)(aL + ao + 512);
            const unsigned char* wt = wb + (size_t)l * 8 + (size_t)nh * 4096;

#pragma unroll
            for (int jg = 0; jg < 4; jg++) {
                uint2 bh0[4], bh1[4], bl0[4], bl1[4];
#pragma unroll
                for (int jj = 0; jj < 4; jj++) {
                    int j = jg * 4 + jj;
                    bh0[jj] = *(const uint2*)(wt + j * 256);
                    bh1[jj] = *(const uint2*)(wt + 8192 + j * 256);
                    bl0[jj] = *(const uint2*)(wt + 16384 + j * 256);
                    bl1[jj] = *(const uint2*)(wt + 24576 + j * 256);
                }
                float (*Cg)[4] = &C[jg * 4];
#pragma unroll
                for (int jj = 0; jj < 4; jj++)
                    mma16816(Cg[jj], ah0.x, ah0.y, ah0.z, ah0.w,
                             bh0[jj].x, bh0[jj].y);
#pragma unroll
                for (int jj = 0; jj < 4; jj++)
                    mma16816(Cg[jj], al0.x, al0.y, al0.z, al0.w,
                             bh0[jj].x, bh0[jj].y);
#pragma unroll
                for (int jj = 0; jj < 4; jj++)
                    mma16816(Cg[jj], ah0.x, ah0.y, ah0.z, ah0.w,
                             bl0[jj].x, bl0[jj].y);
#pragma unroll
                for (int jj = 0; jj < 4; jj++)
                    mma16816(Cg[jj], ah1.x, ah1.y, ah1.z, ah1.w,
                             bh1[jj].x, bh1[jj].y);
#pragma unroll
                for (int jj = 0; jj < 4; jj++)
                    mma16816(Cg[jj], al1.x, al1.y, al1.z, al1.w,
                             bh1[jj].x, bh1[jj].y);
#pragma unroll
                for (int jj = 0; jj < 4; jj++)
                    mma16816(Cg[jj], ah1.x, ah1.y, ah1.z, ah1.w,
                             bl1[jj].x, bl1[jj].y);
            }
            __syncthreads();   // all warps done with this buffer
            if (tid == 0 && q + 2 < 40) {
                int qq = q + 2;
                mbar_expect(mb[qq & 1], CHUNK);
                bulk_g2s(wb_addr[qq & 1], g_Wf + (size_t)qq * CHUNK, CHUNK,
                         mb[qq & 1]);
            }
        }

        // ---- epilogue
        if (g == 4) {
            int n0 = r0 + 16 * m + gid;
            int n1 = n0 + 8;
            int cb = 128 * nh + c2v;
            if (n0 < N) {
                float* o = out + (size_t)n0 * FDIM + cb;
#pragma unroll
                for (int j = 0; j < 16; j++)
                    *(float2*)(o + 8 * j) = make_float2(C[j][0], C[j][1]);
            }
            if (n1 < N) {
                float* o = out + (size_t)n1 * FDIM + cb;
#pragma unroll
                for (int j = 0; j < 16; j++)
                    *(float2*)(o + 8 * j) = make_float2(C[j][2], C[j][3]);
            }
        } else {
            bool storeH = (g == 1 || g == 3);
#pragma unroll
            for (int t = 0; t < 8; t++) {
                float x0 = C[2 * t][0], x1 = C[2 * t][1];
                float x2 = C[2 * t][2], x3 = C[2 * t][3];
                float y0 = C[2 * t + 1][0], y1 = C[2 * t + 1][1];
                float y2 = C[2 * t + 1][2], y3 = C[2 * t + 1][3];
                uint32_t H0, L0, H1, L1, H2, L2, H3, L3;
                bf16split2(siluf(x0), siluf(x1), H0, L0);
                bf16split2(siluf(x2), siluf(x3), H1, L1);
                bf16split2(siluf(y0), siluf(y1), H2, L2);
                bf16split2(siluf(y2), siluf(y3), H3, L3);
                size_t ao = (size_t)((m * 16 + 8 * nh + t) * 32 + l) * 16;
                *(uint4*)(aH + ao) = make_uint4(H0, H1, H2, H3);
                *(uint4*)(aL + ao) = make_uint4(L0, L1, L2, L3);
                if (storeH) {
                    size_t ho = (size_t)((w * 16 + 2 * t) * 32 + l) * 16;
                    *(float4*)(hF + ho) = make_float4(x0, x1, x2, x3);
                    *(float4*)(hF + ho + 512) = make_float4(y0, y1, y2, y3);
                }
            }
            __syncthreads();   // publish A before next GEMM
        }
    }
}

// ---------------------------------------------------------------------------
extern "C" void kernel_launch(void* const* d_in, const int* in_sizes, int n_in,
                              void* d_out, int out_size) {
    int base = (n_in >= 11 && in_sizes[2] == 1) ? 1 : 0;

    const float* x     = (const float*)d_in[0];
    const float* E     = (const float*)d_in[1];
    const void*  seg   = d_in[2 + base];
    const float* Wq    = (const float*)d_in[3 + base];
    const float* bq    = (const float*)d_in[4 + base];
    const float* Wk    = (const float*)d_in[5 + base];
    const float* Wv    = (const float*)d_in[6 + base];
    const float* Wres1 = (const float*)d_in[7 + base];
    const float* Wres2 = (const float*)d_in[8 + base];
    const float* Wout  = (const float*)d_in[9 + base];

    int N = in_sizes[0] / FDIM;
    int B = in_sizes[1];
    if (N > MAXN) N = MAXN;
    if (B > MAXB) B = MAXB;

    detect_kernel<<<1, 1>>>((const int*)seg, N);
    prep_kernel<<<1 + (B + 255) / 256, 256>>>(Wq, Wk, bq, E, B);
    convW_kernel<<<(81920 + 127) / 128, 128>>>(Wres1, Wres2, Wout);
    dot_kernel<<<(N + 7) / 8, 256>>>(x, seg, N);

    int smem_bytes = 196608;
    cudaFuncSetAttribute(chain_mma, cudaFuncAttributeMaxDynamicSharedMemorySize,
                         smem_bytes);
    chain_mma<<<(N + TM - 1) / TM, 256, smem_bytes>>>(seg, Wv, (float*)d_out, N);
}

// round 10
// speedup vs baseline: 3.8699x; 1.2481x over previous
#include <cuda_runtime.h>
#include <cuda_fp16.h>
#include <math.h>
#include <stdint.h>

// ===========================================================================
// ElectronicEmbedding (SpookyNet) — R10: fp16-split HMMA chain.
// Main pass f32-accum, correction passes f16-accum. Warp = 32 rows x 64 cols.
// Producer/consumer mbarrier W ring (no per-chunk syncthreads); named
// barriers per m-group at GEMM boundaries.
// ===========================================================================

#define FDIM 256
#define TM   64
#define MAXN 200704
#define MAXB 4096
#define CHUNK 32768   // one W chunk: 2 ktiles x 32 ntiles, hi+lo fragments
#define NQ 40         // total chunks (5 GEMMs x 8)

__device__ __align__(16) unsigned char g_Wf[5 * 8 * CHUNK];

__device__ float g_u[FDIM];
__device__ float g_c0;
__device__ float g_cf[MAXB];
__device__ float g_ev[MAXB];
__device__ float g_anorm[MAXB];
__device__ float g_a[MAXN];
__device__ int   g_seg64;

// ---------------------------------------------------------------------------
__device__ __forceinline__ uint32_t smem_u32(const void* p) {
    uint32_t a;
    asm("{ .reg .u64 t; cvta.to.shared.u64 t, %1; cvt.u32.u64 %0, t; }"
        : "=r"(a) : "l"(p));
    return a;
}

__device__ __forceinline__ int get_seg(const void* seg, int n) {
    int b;
    if (g_seg64) b = (int)((const long long*)seg)[n];
    else         b = ((const int*)seg)[n];
    if (b < 0) b = 0;
    if (b >= MAXB) b = MAXB - 1;
    return b;
}

__device__ __forceinline__ float siluf(float x) {
    return x * (1.0f / (1.0f + __expf(-x)));
}

// fp16 hi/lo split of two floats -> packed half2 words {low=a, high=b}
__device__ __forceinline__ void f16split2(float a, float b,
                                          uint32_t& hp, uint32_t& lp) {
    __half2 h = __floats2half2_rn(a, b);
    float2 f = __half22float2(h);
    __half2 l = __floats2half2_rn(a - f.x, b - f.y);
    hp = *(uint32_t*)&h;
    lp = *(uint32_t*)&l;
}

// ---------------------------------------------------------------------------
// mbarrier / bulk copy
// ---------------------------------------------------------------------------
__device__ __forceinline__ void mbar_init(uint32_t m, uint32_t cnt) {
    asm volatile("mbarrier.init.shared.b64 [%0], %1;" :: "r"(m), "r"(cnt) : "memory");
}
__device__ __forceinline__ void mbar_expect(uint32_t m, uint32_t bytes) {
    asm volatile("mbarrier.arrive.expect_tx.shared.b64 _, [%0], %1;"
                 :: "r"(m), "r"(bytes) : "memory");
}
__device__ __forceinline__ void mbar_arrive(uint32_t m) {
    asm volatile("mbarrier.arrive.shared.b64 _, [%0];" :: "r"(m) : "memory");
}
__device__ __forceinline__ void mbar_wait(uint32_t m, uint32_t parity) {
    uint32_t done;
    asm volatile(
        "{\n\t.reg .pred p;\n\t"
        "mbarrier.try_wait.parity.acquire.cta.shared::cta.b64 p, [%1], %2;\n\t"
        "selp.b32 %0, 1, 0, p;\n\t}"
        : "=r"(done) : "r"(m), "r"(parity) : "memory");
    while (!done) {
        asm volatile(
            "{\n\t.reg .pred p;\n\t"
            "mbarrier.try_wait.parity.acquire.cta.shared::cta.b64 p, [%1], %2, 0x989680;\n\t"
            "selp.b32 %0, 1, 0, p;\n\t}"
            : "=r"(done) : "r"(m), "r"(parity) : "memory");
    }
}
__device__ __forceinline__ void bulk_g2s(uint32_t dst, const void* src,
                                         uint32_t bytes, uint32_t mbar) {
    asm volatile(
        "cp.async.bulk.shared::cluster.global.mbarrier::complete_tx::bytes "
        "[%0], [%1], %2, [%3];"
        :: "r"(dst), "l"(src), "r"(bytes), "r"(mbar) : "memory");
}
#define FENCE_ASYNC() asm volatile("fence.proxy.async.shared::cta;" ::: "memory")
#define BAR_NAMED(id, cnt) \
    asm volatile("bar.sync %0, %1;" :: "r"(id), "r"(cnt) : "memory")

// fp16 MMA, f32 accumulate (main pass)
__device__ __forceinline__ void mma_f32(float c[4], uint4 a, uint2 b) {
    asm volatile(
        "mma.sync.aligned.m16n8k16.row.col.f32.f16.f16.f32 "
        "{%0,%1,%2,%3}, {%4,%5,%6,%7}, {%8,%9}, {%0,%1,%2,%3};"
        : "+f"(c[0]), "+f"(c[1]), "+f"(c[2]), "+f"(c[3])
        : "r"(a.x), "r"(a.y), "r"(a.z), "r"(a.w), "r"(b.x), "r"(b.y));
}
// fp16 MMA, f16 accumulate (correction passes)
__device__ __forceinline__ void mma_f16(uint32_t c[2], uint4 a, uint2 b) {
    asm volatile(
        "mma.sync.aligned.m16n8k16.row.col.f16.f16.f16.f16 "
        "{%0,%1}, {%2,%3,%4,%5}, {%6,%7}, {%0,%1};"
        : "+r"(c[0]), "+r"(c[1])
        : "r"(a.x), "r"(a.y), "r"(a.z), "r"(a.w), "r"(b.x), "r"(b.y));
}

// ---------------------------------------------------------------------------
// detect / prep
// ---------------------------------------------------------------------------
__global__ void detect_kernel(const int* __restrict__ seg32, int N) {
    int last = seg32[N - 1];
    int prev = seg32[N - 2];
    g_seg64 = (last == 0 && prev > 0) ? 1 : 0;
}

__global__ void prep_kernel(const float* __restrict__ Wq,
                            const float* __restrict__ Wk,
                            const float* __restrict__ bq,
                            const float* __restrict__ E, int B) {
    int tid = threadIdx.x;
    if (blockIdx.x == 0) {
        float s = 0.0f;
#pragma unroll 8
        for (int f = 0; f < FDIM; f++)
            s = fmaf(Wk[f], Wq[f * FDIM + tid], s);
        g_u[tid] = s;
        if (tid == 0) {
            float c = 0.0f;
            for (int f = 0; f < FDIM; f++) c = fmaf(bq[f], Wk[f], c);
            g_c0 = c;
        }
    } else {
        int b = (blockIdx.x - 1) * 256 + tid;
        if (b < B) {
            float e = fabsf(E[b]);
            g_ev[b] = e;
            g_cf[b] = e / fmaxf(e, 1.0f);
            g_anorm[b] = 0.0f;
        }
    }
}

// ---------------------------------------------------------------------------
// dot: 4 rows per warp, front-batched loads.
// ---------------------------------------------------------------------------
__global__ void dot_kernel(const float* __restrict__ x,
                           const void* __restrict__ seg, int N) {
    __shared__ float su[FDIM];
    __shared__ float sc0;
    int tid = threadIdx.x;
    su[tid] = g_u[tid];
    if (tid == 0) sc0 = g_c0;
    __syncthreads();

    int wid = tid >> 5, lane = tid & 31;
    int n0 = (blockIdx.x * 8 + wid) * 4;
    if (n0 >= N) return;

    float4 u0 = *(const float4*)&su[4 * lane];
    float4 u1 = *(const float4*)&su[128 + 4 * lane];

    float p[4];
#pragma unroll
    for (int r = 0; r < 4; r++) {
        int n = n0 + r;
        p[r] = 0.0f;
        if (n < N) {
            const float4* xr = (const float4*)(x + (size_t)n * FDIM);
            float4 xa = xr[lane];
            float4 xb = xr[32 + lane];
            p[r] = xa.x * u0.x + xa.y * u0.y + xa.z * u0.z + xa.w * u0.w +
                   xb.x * u1.x + xb.y * u1.y + xb.z * u1.z + xb.w * u1.w;
        }
    }
#pragma unroll
    for (int r = 0; r < 4; r++)
#pragma unroll
        for (int o = 16; o > 0; o >>= 1)
            p[r] += __shfl_down_sync(0xffffffffu, p[r], o);

    if (lane == 0) {
#pragma unroll
        for (int r = 0; r < 4; r++) {
            int n = n0 + r;
            if (n < N) {
                int b = get_seg(seg, n);
                float d = (p[r] + sc0) * g_cf[b] * 0.0625f;
                float a = fmaxf(d, 0.0f) + log1pf(expf(-fabsf(d)));
                g_a[n] = a;
                atomicAdd(&g_anorm[b], a);
            }
        }
    }
}

// ---------------------------------------------------------------------------
// convW: fp32 W[out][in] -> fragment-ordered fp16 hi/lo chunk images.
// chunk layout: [s(2)][t2(2)][j(32)][l(32)][2 uint32]; chunks: [m(5)][c(8)].
// ---------------------------------------------------------------------------
__global__ void convW_kernel(const float* __restrict__ Wres1,
                             const float* __restrict__ Wres2,
                             const float* __restrict__ Wout) {
    int idx = blockIdx.x * blockDim.x + threadIdx.x;
    if (idx >= 5 * 8 * 2 * 32 * 32) return;   // 81920
    int l  = idx & 31;
    int j  = (idx >> 5) & 31;
    int t2 = (idx >> 10) & 1;
    int c  = (idx >> 11) & 7;
    int m  = idx >> 14;

    const float* Wm;
    switch (m) {
        case 0: Wm = Wres1; break;
        case 1: Wm = Wres2; break;
        case 2: Wm = Wres1 + 65536; break;
        case 3: Wm = Wres2 + 65536; break;
        default: Wm = Wout; break;
    }
    int n  = 8 * j + (l >> 2);
    int k0 = 32 * c + 16 * t2 + (l & 3) * 2;
    const float* p = Wm + n * FDIM + k0;
    uint32_t H0, L0, H1, L1;
    f16split2(p[0], p[1], H0, L0);
    f16split2(p[8], p[9], H1, L1);
    size_t base = (size_t)(m * 8 + c) * CHUNK +
                  (size_t)(((t2 * 32 + j) * 32 + l)) * 8;
    *(uint2*)(g_Wf + base)         = make_uint2(H0, H1);   // hi
    *(uint2*)(g_Wf + base + 16384) = make_uint2(L0, L1);   // lo
}

// ---------------------------------------------------------------------------
// Epilogue store helper: totals -> silu/split A frags (+ optional h fp32).
// Warp (m, nh) owns atiles 2m,2m+1 and ktiles 4nh..4nh+3.
// ---------------------------------------------------------------------------
__device__ __forceinline__ void store_A_frags(float Cm[2][8][4],
                                              unsigned char* aH,
                                              unsigned char* aL,
                                              unsigned char* hF,
                                              int w, int m, int nh, int l,
                                              bool storeH) {
#pragma unroll
    for (int a = 0; a < 2; a++) {
#pragma unroll
        for (int tt = 0; tt < 4; tt++) {
            const float* X = Cm[a][2 * tt];
            const float* Y = Cm[a][2 * tt + 1];
            uint32_t H0, L0, H1, L1, H2, L2, H3, L3;
            f16split2(siluf(X[0]), siluf(X[1]), H0, L0);
            f16split2(siluf(X[2]), siluf(X[3]), H1, L1);
            f16split2(siluf(Y[0]), siluf(Y[1]), H2, L2);
            f16split2(siluf(Y[2]), siluf(Y[3]), H3, L3);
            int slot = (2 * m + a) * 16 + 4 * nh + tt;
            size_t ao = (size_t)(slot * 32 + l) * 16;
            *(uint4*)(aH + ao) = make_uint4(H0, H1, H2, H3);
            *(uint4*)(aL + ao) = make_uint4(L0, L1, L2, L3);
            if (storeH) {
                size_t ho = (size_t)((w * 16 + a * 8 + 2 * tt) * 32 + l) * 16;
                *(float4*)(hF + ho) = make_float4(X[0], X[1], X[2], X[3]);
                *(float4*)(hF + ho + 512) = make_float4(Y[0], Y[1], Y[2], Y[3]);
            }
        }
    }
}

// ---------------------------------------------------------------------------
// chain_mma: 64 rows/CTA, 256 threads (8 warps). warp = (m = w>>2, nh = w&3)
// owning rows 32m..32m+31 x cols 64nh..64nh+63.
// SMEM: aH 32K | aL 32K | hF 64K | wbuf0 32K | wbuf1 32K = 192K.
// ---------------------------------------------------------------------------
__global__ __launch_bounds__(256, 1)
void chain_mma(const void* __restrict__ seg,
               const float* __restrict__ Wv,
               float* __restrict__ out, int N) {
    extern __shared__ __align__(1024) unsigned char dyn[];
    unsigned char* aH = dyn;
    unsigned char* aL = dyn + 32768;
    unsigned char* hF = dyn + 65536;
    uint32_t wb_addr[2] = { smem_u32(dyn + 131072), smem_u32(dyn + 163840) };
    unsigned char* wb_ptr[2] = { dyn + 131072, dyn + 163840 };

    __shared__ __align__(8) unsigned long long s_mb[4];  // full0 full1 empty0 empty1
    __shared__ float s_sv[TM];
    __shared__ float s_wv[FDIM];

    int tid = threadIdx.x;
    int w = tid >> 5, l = tid & 31;
    int m = w >> 2, nh = w & 3;
    int gid = l >> 2;
    int c2v = (l & 3) * 2;
    int r0 = blockIdx.x * TM;

    uint32_t mb_full[2]  = { smem_u32(&s_mb[0]), smem_u32(&s_mb[1]) };
    uint32_t mb_empty[2] = { smem_u32(&s_mb[2]), smem_u32(&s_mb[3]) };

    if (tid == 0) {
        mbar_init(mb_full[0], 1);
        mbar_init(mb_full[1], 1);
        mbar_init(mb_empty[0], 8);
        mbar_init(mb_empty[1], 8);
        FENCE_ASYNC();
    }
    if (tid < TM) {
        int n = r0 + tid;
        float s = 0.0f;
        if (n < N) {
            int b = get_seg(seg, n);
            s = g_a[n] / (g_anorm[b] + 1e-8f) * g_ev[b];
        }
        s_sv[tid] = s;
    }
    s_wv[tid] = Wv[tid];
    __syncthreads();

    if (tid == 0) {
        mbar_expect(mb_full[0], CHUNK);
        bulk_g2s(wb_addr[0], g_Wf, CHUNK, mb_full[0]);
        mbar_expect(mb_full[1], CHUNK);
        bulk_g2s(wb_addr[1], g_Wf + CHUNK, CHUNK, mb_full[1]);
    }

    float    Cm[2][8][4];
    uint32_t Cc[2][8][2];

    // ---- init: h0 = s (x) Wv into Cm; store A = split(silu(h0)) and h fp32.
    {
#pragma unroll
        for (int a = 0; a < 2; a++) {
            int rlo = 16 * (2 * m + a) + gid;
            float s0 = s_sv[rlo];
            float s1 = s_sv[rlo + 8];
#pragma unroll
            for (int jj = 0; jj < 8; jj++) {
                int col = 8 * (8 * nh + jj) + c2v;
                float w0 = s_wv[col], w1 = s_wv[col + 1];
                Cm[a][jj][0] = s0 * w0;
                Cm[a][jj][1] = s0 * w1;
                Cm[a][jj][2] = s1 * w0;
                Cm[a][jj][3] = s1 * w1;
            }
        }
        store_A_frags(Cm, aH, aL, hF, w, m, nh, l, true);
    }
    __syncthreads();

#pragma unroll 1
    for (int g = 0; g < 5; g++) {
        // ---- accumulator init
        if (g == 1 || g == 3) {
#pragma unroll
            for (int a = 0; a < 2; a++)
#pragma unroll
                for (int jj = 0; jj < 8; jj++) {
                    float4 hv = *(float4*)(hF +
                        (size_t)((w * 16 + a * 8 + jj) * 32 + l) * 16);
                    Cm[a][jj][0] = hv.x; Cm[a][jj][1] = hv.y;
                    Cm[a][jj][2] = hv.z; Cm[a][jj][3] = hv.w;
                }
        } else {
#pragma unroll
            for (int a = 0; a < 2; a++)
#pragma unroll
                for (int jj = 0; jj < 8; jj++)
                    Cm[a][jj][0] = Cm[a][jj][1] = Cm[a][jj][2] = Cm[a][jj][3] = 0.0f;
        }
#pragma unroll
        for (int a = 0; a < 2; a++)
#pragma unroll
            for (int jj = 0; jj < 8; jj++)
                Cc[a][jj][0] = Cc[a][jj][1] = 0u;

        // ---- mainloop: 8 k-chunks of 32
#pragma unroll 1
        for (int c = 0; c < 8; c++) {
            int q = 8 * g + c;
            int s = q & 1;
            mbar_wait(mb_full[s], (uint32_t)((q >> 1) & 1));
            const unsigned char* wt = wb_ptr[s] + (size_t)l * 8 + nh * 2048;

#pragma unroll
            for (int t = 0; t < 2; t++) {
                int slot0 = (2 * m + 0) * 16 + 2 * c + t;
                int slot1 = (2 * m + 1) * 16 + 2 * c + t;
                uint4 ah0 = *(const uint4*)(aH + (size_t)(slot0 * 32 + l) * 16);
                uint4 ah1 = *(const uint4*)(aH + (size_t)(slot1 * 32 + l) * 16);
                uint4 al0 = *(const uint4*)(aL + (size_t)(slot0 * 32 + l) * 16);
                uint4 al1 = *(const uint4*)(aL + (size_t)(slot1 * 32 + l) * 16);
                const unsigned char* wtt = wt + t * 8192;
#pragma unroll
                for (int jj = 0; jj < 8; jj++) {
                    uint2 bh = *(const uint2*)(wtt + jj * 256);
                    uint2 bl = *(const uint2*)(wtt + 16384 + jj * 256);
                    mma_f32(Cm[0][jj], ah0, bh);
                    mma_f32(Cm[1][jj], ah1, bh);
                    mma_f16(Cc[0][jj], al0, bh);
                    mma_f16(Cc[1][jj], al1, bh);
                    mma_f16(Cc[0][jj], ah0, bl);
                    mma_f16(Cc[1][jj], ah1, bl);
                }
            }
            if (l == 0) mbar_arrive(mb_empty[s]);
            if (tid == 0 && q + 2 < NQ) {
                int qq = q + 2;
                mbar_wait(mb_empty[qq & 1], (uint32_t)(((qq >> 1) + 1) & 1));
                mbar_expect(mb_full[qq & 1], CHUNK);
                bulk_g2s(wb_addr[qq & 1], g_Wf + (size_t)qq * CHUNK, CHUNK,
                         mb_full[qq & 1]);
            }
        }

        BAR_NAMED(1 + m, 128);   // m-group done reading A

        // ---- merge f16 corrections into f32 totals
#pragma unroll
        for (int a = 0; a < 2; a++)
#pragma unroll
            for (int jj = 0; jj < 8; jj++) {
                float2 c01 = __half22float2(*(__half2*)&Cc[a][jj][0]);
                float2 c23 = __half22float2(*(__half2*)&Cc[a][jj][1]);
                Cm[a][jj][0] += c01.x;
                Cm[a][jj][1] += c01.y;
                Cm[a][jj][2] += c23.x;
                Cm[a][jj][3] += c23.y;
            }

        // ---- epilogue
        if (g == 4) {
#pragma unroll
            for (int a = 0; a < 2; a++) {
                int rlo = r0 + 16 * (2 * m + a) + gid;
#pragma unroll
                for (int jj = 0; jj < 8; jj++) {
                    int col = 8 * (8 * nh + jj) + c2v;
                    if (rlo < N)
                        *(float2*)(out + (size_t)rlo * FDIM + col) =
                            make_float2(Cm[a][jj][0], Cm[a][jj][1]);
                    if (rlo + 8 < N)
                        *(float2*)(out + (size_t)(rlo + 8) * FDIM + col) =
                            make_float2(Cm[a][jj][2], Cm[a][jj][3]);
                }
            }
        } else {
            store_A_frags(Cm, aH, aL, hF, w, m, nh, l, (g == 1 || g == 3));
            BAR_NAMED(1 + m, 128);   // publish A before next GEMM reads
        }
    }
}

// ---------------------------------------------------------------------------
extern "C" void kernel_launch(void* const* d_in, const int* in_sizes, int n_in,
                              void* d_out, int out_size) {
    int base = (n_in >= 11 && in_sizes[2] == 1) ? 1 : 0;

    const float* x     = (const float*)d_in[0];
    const float* E     = (const float*)d_in[1];
    const void*  seg   = d_in[2 + base];
    const float* Wq    = (const float*)d_in[3 + base];
    const float* bq    = (const float*)d_in[4 + base];
    const float* Wk    = (const float*)d_in[5 + base];
    const float* Wv    = (const float*)d_in[6 + base];
    const float* Wres1 = (const float*)d_in[7 + base];
    const float* Wres2 = (const float*)d_in[8 + base];
    const float* Wout  = (const float*)d_in[9 + base];

    int N = in_sizes[0] / FDIM;
    int B = in_sizes[1];
    if (N > MAXN) N = MAXN;
    if (B > MAXB) B = MAXB;

    detect_kernel<<<1, 1>>>((const int*)seg, N);
    prep_kernel<<<1 + (B + 255) / 256, 256>>>(Wq, Wk, bq, E, B);
    convW_kernel<<<(81920 + 127) / 128, 128>>>(Wres1, Wres2, Wout);
    dot_kernel<<<(N + 31) / 32, 256>>>(x, seg, N);

    int smem_bytes = 196608;
    cudaFuncSetAttribute(chain_mma, cudaFuncAttributeMaxDynamicSharedMemorySize,
                         smem_bytes);
    chain_mma<<<(N + TM - 1) / TM, 256, smem_bytes>>>(seg, Wv, (float*)d_out, N);
}

// round 12
// speedup vs baseline: 4.8414x; 1.2510x over previous
#include <cuda_runtime.h>
#include <cuda_fp16.h>
#include <math.h>
#include <stdint.h>

// ===========================================================================
// ElectronicEmbedding (SpookyNet) — R12: fp16-split HMMA chain, single
// correction pass (A-side only), depth-4 W ring. (R11 + convW grid fix.)
// Main pass f32-accum (rt~16), correction Al*Wh f16-accum (rt~8).
// Warp = 32 rows x 64 cols. Producer/consumer mbarrier W ring.
// ===========================================================================

#define FDIM 256
#define TM   64
#define MAXN 200704
#define MAXB 4096
#define CHUNK 16384   // one W chunk: 2 ktiles x 32 ntiles, hi fragments only
#define NQ 40         // total chunks (5 GEMMs x 8)
#define RING 4

__device__ __align__(16) unsigned char g_Wf[5 * 8 * CHUNK];

__device__ float g_u[FDIM];
__device__ float g_c0;
__device__ float g_cf[MAXB];
__device__ float g_ev[MAXB];
__device__ float g_anorm[MAXB];
__device__ float g_a[MAXN];
__device__ int   g_seg64;

// ---------------------------------------------------------------------------
__device__ __forceinline__ uint32_t smem_u32(const void* p) {
    uint32_t a;
    asm("{ .reg .u64 t; cvta.to.shared.u64 t, %1; cvt.u32.u64 %0, t; }"
        : "=r"(a) : "l"(p));
    return a;
}

__device__ __forceinline__ int get_seg(const void* seg, int n) {
    int b;
    if (g_seg64) b = (int)((const long long*)seg)[n];
    else         b = ((const int*)seg)[n];
    if (b < 0) b = 0;
    if (b >= MAXB) b = MAXB - 1;
    return b;
}

__device__ __forceinline__ float siluf(float x) {
    return x * (1.0f / (1.0f + __expf(-x)));
}

// fp16 hi/lo split of two floats -> packed half2 words {low=a, high=b}
__device__ __forceinline__ void f16split2(float a, float b,
                                          uint32_t& hp, uint32_t& lp) {
    __half2 h = __floats2half2_rn(a, b);
    float2 f = __half22float2(h);
    __half2 l = __floats2half2_rn(a - f.x, b - f.y);
    hp = *(uint32_t*)&h;
    lp = *(uint32_t*)&l;
}
__device__ __forceinline__ uint32_t f16pack2(float a, float b) {
    __half2 h = __floats2half2_rn(a, b);
    return *(uint32_t*)&h;
}

// ---------------------------------------------------------------------------
// mbarrier / bulk copy
// ---------------------------------------------------------------------------
__device__ __forceinline__ void mbar_init(uint32_t m, uint32_t cnt) {
    asm volatile("mbarrier.init.shared.b64 [%0], %1;" :: "r"(m), "r"(cnt) : "memory");
}
__device__ __forceinline__ void mbar_expect(uint32_t m, uint32_t bytes) {
    asm volatile("mbarrier.arrive.expect_tx.shared.b64 _, [%0], %1;"
                 :: "r"(m), "r"(bytes) : "memory");
}
__device__ __forceinline__ void mbar_arrive(uint32_t m) {
    asm volatile("mbarrier.arrive.shared.b64 _, [%0];" :: "r"(m) : "memory");
}
__device__ __forceinline__ void mbar_wait(uint32_t m, uint32_t parity) {
    uint32_t done;
    asm volatile(
        "{\n\t.reg .pred p;\n\t"
        "mbarrier.try_wait.parity.acquire.cta.shared::cta.b64 p, [%1], %2;\n\t"
        "selp.b32 %0, 1, 0, p;\n\t}"
        : "=r"(done) : "r"(m), "r"(parity) : "memory");
    while (!done) {
        asm volatile(
            "{\n\t.reg .pred p;\n\t"
            "mbarrier.try_wait.parity.acquire.cta.shared::cta.b64 p, [%1], %2, 0x989680;\n\t"
            "selp.b32 %0, 1, 0, p;\n\t}"
            : "=r"(done) : "r"(m), "r"(parity) : "memory");
    }
}
__device__ __forceinline__ void bulk_g2s(uint32_t dst, const void* src,
                                         uint32_t bytes, uint32_t mbar) {
    asm volatile(
        "cp.async.bulk.shared::cluster.global.mbarrier::complete_tx::bytes "
        "[%0], [%1], %2, [%3];"
        :: "r"(dst), "l"(src), "r"(bytes), "r"(mbar) : "memory");
}
#define FENCE_ASYNC() asm volatile("fence.proxy.async.shared::cta;" ::: "memory")
#define BAR_NAMED(id, cnt) \
    asm volatile("bar.sync %0, %1;" :: "r"(id), "r"(cnt) : "memory")

// fp16 MMA, f32 accumulate (main pass)
__device__ __forceinline__ void mma_f32(float c[4], uint4 a, uint2 b) {
    asm volatile(
        "mma.sync.aligned.m16n8k16.row.col.f32.f16.f16.f32 "
        "{%0,%1,%2,%3}, {%4,%5,%6,%7}, {%8,%9}, {%0,%1,%2,%3};"
        : "+f"(c[0]), "+f"(c[1]), "+f"(c[2]), "+f"(c[3])
        : "r"(a.x), "r"(a.y), "r"(a.z), "r"(a.w), "r"(b.x), "r"(b.y));
}
// fp16 MMA, f16 accumulate (correction pass)
__device__ __forceinline__ void mma_f16(uint32_t c[2], uint4 a, uint2 b) {
    asm volatile(
        "mma.sync.aligned.m16n8k16.row.col.f16.f16.f16.f16 "
        "{%0,%1}, {%2,%3,%4,%5}, {%6,%7}, {%0,%1};"
        : "+r"(c[0]), "+r"(c[1])
        : "r"(a.x), "r"(a.y), "r"(a.z), "r"(a.w), "r"(b.x), "r"(b.y));
}

// ---------------------------------------------------------------------------
// detect / prep
// ---------------------------------------------------------------------------
__global__ void detect_kernel(const int* __restrict__ seg32, int N) {
    int last = seg32[N - 1];
    int prev = seg32[N - 2];
    g_seg64 = (last == 0 && prev > 0) ? 1 : 0;
}

__global__ void prep_kernel(const float* __restrict__ Wq,
                            const float* __restrict__ Wk,
                            const float* __restrict__ bq,
                            const float* __restrict__ E, int B) {
    int tid = threadIdx.x;
    if (blockIdx.x == 0) {
        float s = 0.0f;
#pragma unroll 8
        for (int f = 0; f < FDIM; f++)
            s = fmaf(Wk[f], Wq[f * FDIM + tid], s);
        g_u[tid] = s;
        if (tid == 0) {
            float c = 0.0f;
            for (int f = 0; f < FDIM; f++) c = fmaf(bq[f], Wk[f], c);
            g_c0 = c;
        }
    } else {
        int b = (blockIdx.x - 1) * 256 + tid;
        if (b < B) {
            float e = fabsf(E[b]);
            g_ev[b] = e;
            g_cf[b] = e / fmaxf(e, 1.0f);
            g_anorm[b] = 0.0f;
        }
    }
}

// ---------------------------------------------------------------------------
// dot: 4 rows per warp, front-batched loads.
// ---------------------------------------------------------------------------
__global__ void dot_kernel(const float* __restrict__ x,
                           const void* __restrict__ seg, int N) {
    __shared__ float su[FDIM];
    __shared__ float sc0;
    int tid = threadIdx.x;
    su[tid] = g_u[tid];
    if (tid == 0) sc0 = g_c0;
    __syncthreads();

    int wid = tid >> 5, lane = tid & 31;
    int n0 = (blockIdx.x * 8 + wid) * 4;
    if (n0 >= N) return;

    float4 u0 = *(const float4*)&su[4 * lane];
    float4 u1 = *(const float4*)&su[128 + 4 * lane];

    float p[4];
#pragma unroll
    for (int r = 0; r < 4; r++) {
        int n = n0 + r;
        p[r] = 0.0f;
        if (n < N) {
            const float4* xr = (const float4*)(x + (size_t)n * FDIM);
            float4 xa = xr[lane];
            float4 xb = xr[32 + lane];
            p[r] = xa.x * u0.x + xa.y * u0.y + xa.z * u0.z + xa.w * u0.w +
                   xb.x * u1.x + xb.y * u1.y + xb.z * u1.z + xb.w * u1.w;
        }
    }
#pragma unroll
    for (int r = 0; r < 4; r++)
#pragma unroll
        for (int o = 16; o > 0; o >>= 1)
            p[r] += __shfl_down_sync(0xffffffffu, p[r], o);

    if (lane == 0) {
#pragma unroll
        for (int r = 0; r < 4; r++) {
            int n = n0 + r;
            if (n < N) {
                int b = get_seg(seg, n);
                float d = (p[r] + sc0) * g_cf[b] * 0.0625f;
                float a = fmaxf(d, 0.0f) + log1pf(expf(-fabsf(d)));
                g_a[n] = a;
                atomicAdd(&g_anorm[b], a);
            }
        }
    }
}

// ---------------------------------------------------------------------------
// convW: fp32 W[out][in] -> fragment-ordered fp16 (hi only) chunk images.
// chunk layout: [t2(2)][j(32)][l(32)][2 uint32] = 16KB; chunks: [m(5)][c(8)].
// Index space: [m 5][c 8][t2 2][j 32][l 32] = 81920 threads.
// ---------------------------------------------------------------------------
#define CONVW_THREADS (5 * 8 * 2 * 32 * 32)   // 81920

__global__ void convW_kernel(const float* __restrict__ Wres1,
                             const float* __restrict__ Wres2,
                             const float* __restrict__ Wout) {
    int idx = blockIdx.x * blockDim.x + threadIdx.x;
    if (idx >= CONVW_THREADS) return;
    int l  = idx & 31;
    int j  = (idx >> 5) & 31;
    int t2 = (idx >> 10) & 1;
    int c  = (idx >> 11) & 7;
    int m  = idx >> 14;
    if (m >= 5) return;

    const float* Wm;
    switch (m) {
        case 0: Wm = Wres1; break;
        case 1: Wm = Wres2; break;
        case 2: Wm = Wres1 + 65536; break;
        case 3: Wm = Wres2 + 65536; break;
        default: Wm = Wout; break;
    }
    int n  = 8 * j + (l >> 2);
    int k0 = 32 * c + 16 * t2 + (l & 3) * 2;
    const float* p = Wm + n * FDIM + k0;
    uint32_t H0 = f16pack2(p[0], p[1]);
    uint32_t H1 = f16pack2(p[8], p[9]);
    size_t base = (size_t)(m * 8 + c) * CHUNK +
                  (size_t)(((t2 * 32 + j) * 32 + l)) * 8;
    *(uint2*)(g_Wf + base) = make_uint2(H0, H1);
}

// ---------------------------------------------------------------------------
// Epilogue store helper: totals -> silu/split A frags (+ optional h fp32).
// ---------------------------------------------------------------------------
__device__ __forceinline__ void store_A_frags(float Cm[2][8][4],
                                              unsigned char* aH,
                                              unsigned char* aL,
                                              unsigned char* hF,
                                              int w, int m, int nh, int l,
                                              bool storeH) {
#pragma unroll
    for (int a = 0; a < 2; a++) {
#pragma unroll
        for (int tt = 0; tt < 4; tt++) {
            const float* X = Cm[a][2 * tt];
            const float* Y = Cm[a][2 * tt + 1];
            uint32_t H0, L0, H1, L1, H2, L2, H3, L3;
            f16split2(siluf(X[0]), siluf(X[1]), H0, L0);
            f16split2(siluf(X[2]), siluf(X[3]), H1, L1);
            f16split2(siluf(Y[0]), siluf(Y[1]), H2, L2);
            f16split2(siluf(Y[2]), siluf(Y[3]), H3, L3);
            int slot = (2 * m + a) * 16 + 4 * nh + tt;
            size_t ao = (size_t)(slot * 32 + l) * 16;
            *(uint4*)(aH + ao) = make_uint4(H0, H1, H2, H3);
            *(uint4*)(aL + ao) = make_uint4(L0, L1, L2, L3);
            if (storeH) {
                size_t ho = (size_t)((w * 16 + a * 8 + 2 * tt) * 32 + l) * 16;
                *(float4*)(hF + ho) = make_float4(X[0], X[1], X[2], X[3]);
                *(float4*)(hF + ho + 512) = make_float4(Y[0], Y[1], Y[2], Y[3]);
            }
        }
    }
}

// ---------------------------------------------------------------------------
// chain_mma: 64 rows/CTA, 256 threads (8 warps). warp = (m = w>>2, nh = w&3)
// owning rows 32m..32m+31 x cols 64nh..64nh+63.
// SMEM: aH 32K | aL 32K | hF 64K | W ring 4x16K = 192K.
// ---------------------------------------------------------------------------
__global__ __launch_bounds__(256, 1)
void chain_mma(const void* __restrict__ seg,
               const float* __restrict__ Wv,
               float* __restrict__ out, int N) {
    extern __shared__ __align__(1024) unsigned char dyn[];
    unsigned char* aH = dyn;
    unsigned char* aL = dyn + 32768;
    unsigned char* hF = dyn + 65536;
    uint32_t wb_addr[RING];
    unsigned char* wb_ptr[RING];
#pragma unroll
    for (int i = 0; i < RING; i++) {
        wb_ptr[i] = dyn + 131072 + i * CHUNK;
        wb_addr[i] = smem_u32(wb_ptr[i]);
    }

    __shared__ __align__(8) unsigned long long s_mb[2 * RING];
    __shared__ float s_sv[TM];
    __shared__ float s_wv[FDIM];

    int tid = threadIdx.x;
    int w = tid >> 5, l = tid & 31;
    int m = w >> 2, nh = w & 3;
    int gid = l >> 2;
    int c2v = (l & 3) * 2;
    int r0 = blockIdx.x * TM;

    uint32_t mb_full[RING], mb_empty[RING];
#pragma unroll
    for (int i = 0; i < RING; i++) {
        mb_full[i]  = smem_u32(&s_mb[i]);
        mb_empty[i] = smem_u32(&s_mb[RING + i]);
    }

    if (tid == 0) {
#pragma unroll
        for (int i = 0; i < RING; i++) {
            mbar_init(mb_full[i], 1);
            mbar_init(mb_empty[i], 8);
        }
        FENCE_ASYNC();
    }
    if (tid < TM) {
        int n = r0 + tid;
        float s = 0.0f;
        if (n < N) {
            int b = get_seg(seg, n);
            s = g_a[n] / (g_anorm[b] + 1e-8f) * g_ev[b];
        }
        s_sv[tid] = s;
    }
    s_wv[tid] = Wv[tid];
    __syncthreads();

    if (tid == 0) {
#pragma unroll
        for (int i = 0; i < RING; i++) {
            mbar_expect(mb_full[i], CHUNK);
            bulk_g2s(wb_addr[i], g_Wf + (size_t)i * CHUNK, CHUNK, mb_full[i]);
        }
    }

    float    Cm[2][8][4];
    uint32_t Cc[2][8][2];

    // ---- init: h0 = s (x) Wv into Cm; store A = split(silu(h0)) and h fp32.
    {
#pragma unroll
        for (int a = 0; a < 2; a++) {
            int rlo = 16 * (2 * m + a) + gid;
            float s0 = s_sv[rlo];
            float s1 = s_sv[rlo + 8];
#pragma unroll
            for (int jj = 0; jj < 8; jj++) {
                int col = 8 * (8 * nh + jj) + c2v;
                float w0 = s_wv[col], w1 = s_wv[col + 1];
                Cm[a][jj][0] = s0 * w0;
                Cm[a][jj][1] = s0 * w1;
                Cm[a][jj][2] = s1 * w0;
                Cm[a][jj][3] = s1 * w1;
            }
        }
        store_A_frags(Cm, aH, aL, hF, w, m, nh, l, true);
    }
    __syncthreads();

#pragma unroll 1
    for (int g = 0; g < 5; g++) {
        // ---- accumulator init
        if (g == 1 || g == 3) {
#pragma unroll
            for (int a = 0; a < 2; a++)
#pragma unroll
                for (int jj = 0; jj < 8; jj++) {
                    float4 hv = *(float4*)(hF +
                        (size_t)((w * 16 + a * 8 + jj) * 32 + l) * 16);
                    Cm[a][jj][0] = hv.x; Cm[a][jj][1] = hv.y;
                    Cm[a][jj][2] = hv.z; Cm[a][jj][3] = hv.w;
                }
        } else {
#pragma unroll
            for (int a = 0; a < 2; a++)
#pragma unroll
                for (int jj = 0; jj < 8; jj++)
                    Cm[a][jj][0] = Cm[a][jj][1] = Cm[a][jj][2] = Cm[a][jj][3] = 0.0f;
        }
#pragma unroll
        for (int a = 0; a < 2; a++)
#pragma unroll
            for (int jj = 0; jj < 8; jj++)
                Cc[a][jj][0] = Cc[a][jj][1] = 0u;

        // ---- mainloop: 8 k-chunks of 32
#pragma unroll 1
        for (int c = 0; c < 8; c++) {
            int q = 8 * g + c;
            int s = q & (RING - 1);
            mbar_wait(mb_full[s], (uint32_t)((q >> 2) & 1));
            const unsigned char* wt = wb_ptr[s] + (size_t)l * 8 + nh * 2048;

#pragma unroll
            for (int t = 0; t < 2; t++) {
                int slot0 = (2 * m + 0) * 16 + 2 * c + t;
                int slot1 = (2 * m + 1) * 16 + 2 * c + t;
                uint4 ah0 = *(const uint4*)(aH + (size_t)(slot0 * 32 + l) * 16);
                uint4 ah1 = *(const uint4*)(aH + (size_t)(slot1 * 32 + l) * 16);
                uint4 al0 = *(const uint4*)(aL + (size_t)(slot0 * 32 + l) * 16);
                uint4 al1 = *(const uint4*)(aL + (size_t)(slot1 * 32 + l) * 16);
                const unsigned char* wtt = wt + t * 8192;
#pragma unroll
                for (int jj = 0; jj < 8; jj++) {
                    uint2 bh = *(const uint2*)(wtt + jj * 256);
                    mma_f32(Cm[0][jj], ah0, bh);
                    mma_f32(Cm[1][jj], ah1, bh);
                    mma_f16(Cc[0][jj], al0, bh);
                    mma_f16(Cc[1][jj], al1, bh);
                }
            }
            if (l == 0) mbar_arrive(mb_empty[s]);
            if (tid == 0 && q + RING < NQ) {
                int qq = q + RING;
                int fs = qq & (RING - 1);
                mbar_wait(mb_empty[fs], (uint32_t)(((qq >> 2) + 1) & 1));
                mbar_expect(mb_full[fs], CHUNK);
                bulk_g2s(wb_addr[fs], g_Wf + (size_t)qq * CHUNK, CHUNK,
                         mb_full[fs]);
            }
        }

        BAR_NAMED(1 + m, 128);   // m-group done reading A

        // ---- merge f16 correction into f32 totals
#pragma unroll
        for (int a = 0; a < 2; a++)
#pragma unroll
            for (int jj = 0; jj < 8; jj++) {
                float2 c01 = __half22float2(*(__half2*)&Cc[a][jj][0]);
                float2 c23 = __half22float2(*(__half2*)&Cc[a][jj][1]);
                Cm[a][jj][0] += c01.x;
                Cm[a][jj][1] += c01.y;
                Cm[a][jj][2] += c23.x;
                Cm[a][jj][3] += c23.y;
            }

        // ---- epilogue
        if (g == 4) {
#pragma unroll
            for (int a = 0; a < 2; a++) {
                int rlo = r0 + 16 * (2 * m + a) + gid;
#pragma unroll
                for (int jj = 0; jj < 8; jj++) {
                    int col = 8 * (8 * nh + jj) + c2v;
                    if (rlo < N)
                        *(float2*)(out + (size_t)rlo * FDIM + col) =
                            make_float2(Cm[a][jj][0], Cm[a][jj][1]);
                    if (rlo + 8 < N)
                        *(float2*)(out + (size_t)(rlo + 8) * FDIM + col) =
                            make_float2(Cm[a][jj][2], Cm[a][jj][3]);
                }
            }
        } else {
            store_A_frags(Cm, aH, aL, hF, w, m, nh, l, (g == 1 || g == 3));
            BAR_NAMED(1 + m, 128);   // publish A before next GEMM reads
        }
    }
}

// ---------------------------------------------------------------------------
extern "C" void kernel_launch(void* const* d_in, const int* in_sizes, int n_in,
                              void* d_out, int out_size) {
    int base = (n_in >= 11 && in_sizes[2] == 1) ? 1 : 0;

    const float* x     = (const float*)d_in[0];
    const float* E     = (const float*)d_in[1];
    const void*  seg   = d_in[2 + base];
    const float* Wq    = (const float*)d_in[3 + base];
    const float* bq    = (const float*)d_in[4 + base];
    const float* Wk    = (const float*)d_in[5 + base];
    const float* Wv    = (const float*)d_in[6 + base];
    const float* Wres1 = (const float*)d_in[7 + base];
    const float* Wres2 = (const float*)d_in[8 + base];
    const float* Wout  = (const float*)d_in[9 + base];

    int N = in_sizes[0] / FDIM;
    int B = in_sizes[1];
    if (N > MAXN) N = MAXN;
    if (B > MAXB) B = MAXB;

    detect_kernel<<<1, 1>>>((const int*)seg, N);
    prep_kernel<<<1 + (B + 255) / 256, 256>>>(Wq, Wk, bq, E, B);
    convW_kernel<<<(CONVW_THREADS + 127) / 128, 128>>>(Wres1, Wres2, Wout);
    dot_kernel<<<(N + 31) / 32, 256>>>(x, seg, N);

    int smem_bytes = 196608;
    cudaFuncSetAttribute(chain_mma, cudaFuncAttributeMaxDynamicSharedMemorySize,
                         smem_bytes);
    chain_mma<<<(N + TM - 1) / TM, 256, smem_bytes>>>(seg, Wv, (float*)d_out, N);
}

// round 13
// speedup vs baseline: 5.6621x; 1.1695x over previous
#include <cuda_runtime.h>
#include <cuda_fp16.h>
#include <math.h>
#include <stdint.h>

// ===========================================================================
// ElectronicEmbedding (SpookyNet) — R13: pure fp16 HMMA chain (no correction
// passes), residual h in registers, depth-4 W ring.
// All MMAs f32-accum (rt~16). Warp = 32 rows x 64 cols.
// ===========================================================================

#define FDIM 256
#define TM   64
#define MAXN 200704
#define MAXB 4096
#define CHUNK 16384   // one W chunk: 2 ktiles x 32 ntiles, fp16 fragments
#define NQ 40         // total chunks (5 GEMMs x 8)
#define RING 4

__device__ __align__(16) unsigned char g_Wf[5 * 8 * CHUNK];

__device__ float g_u[FDIM];
__device__ float g_c0;
__device__ float g_cf[MAXB];
__device__ float g_ev[MAXB];
__device__ float g_anorm[MAXB];
__device__ float g_a[MAXN];
__device__ int   g_seg64;

// ---------------------------------------------------------------------------
__device__ __forceinline__ uint32_t smem_u32(const void* p) {
    uint32_t a;
    asm("{ .reg .u64 t; cvta.to.shared.u64 t, %1; cvt.u32.u64 %0, t; }"
        : "=r"(a) : "l"(p));
    return a;
}

__device__ __forceinline__ int get_seg(const void* seg, int n) {
    int b;
    if (g_seg64) b = (int)((const long long*)seg)[n];
    else         b = ((const int*)seg)[n];
    if (b < 0) b = 0;
    if (b >= MAXB) b = MAXB - 1;
    return b;
}

__device__ __forceinline__ float siluf(float x) {
    return x * (1.0f / (1.0f + __expf(-x)));
}

__device__ __forceinline__ uint32_t f16pack2(float a, float b) {
    __half2 h = __floats2half2_rn(a, b);
    return *(uint32_t*)&h;
}

// ---------------------------------------------------------------------------
// mbarrier / bulk copy
// ---------------------------------------------------------------------------
__device__ __forceinline__ void mbar_init(uint32_t m, uint32_t cnt) {
    asm volatile("mbarrier.init.shared.b64 [%0], %1;" :: "r"(m), "r"(cnt) : "memory");
}
__device__ __forceinline__ void mbar_expect(uint32_t m, uint32_t bytes) {
    asm volatile("mbarrier.arrive.expect_tx.shared.b64 _, [%0], %1;"
                 :: "r"(m), "r"(bytes) : "memory");
}
__device__ __forceinline__ void mbar_arrive(uint32_t m) {
    asm volatile("mbarrier.arrive.shared.b64 _, [%0];" :: "r"(m) : "memory");
}
__device__ __forceinline__ void mbar_wait(uint32_t m, uint32_t parity) {
    uint32_t done;
    asm volatile(
        "{\n\t.reg .pred p;\n\t"
        "mbarrier.try_wait.parity.acquire.cta.shared::cta.b64 p, [%1], %2;\n\t"
        "selp.b32 %0, 1, 0, p;\n\t}"
        : "=r"(done) : "r"(m), "r"(parity) : "memory");
    while (!done) {
        asm volatile(
            "{\n\t.reg .pred p;\n\t"
            "mbarrier.try_wait.parity.acquire.cta.shared::cta.b64 p, [%1], %2, 0x989680;\n\t"
            "selp.b32 %0, 1, 0, p;\n\t}"
            : "=r"(done) : "r"(m), "r"(parity) : "memory");
    }
}
__device__ __forceinline__ void bulk_g2s(uint32_t dst, const void* src,
                                         uint32_t bytes, uint32_t mbar) {
    asm volatile(
        "cp.async.bulk.shared::cluster.global.mbarrier::complete_tx::bytes "
        "[%0], [%1], %2, [%3];"
        :: "r"(dst), "l"(src), "r"(bytes), "r"(mbar) : "memory");
}
#define FENCE_ASYNC() asm volatile("fence.proxy.async.shared::cta;" ::: "memory")
#define BAR_NAMED(id, cnt) \
    asm volatile("bar.sync %0, %1;" :: "r"(id), "r"(cnt) : "memory")

// fp16 MMA, f32 accumulate
__device__ __forceinline__ void mma_f32(float c[4], uint4 a, uint2 b) {
    asm volatile(
        "mma.sync.aligned.m16n8k16.row.col.f32.f16.f16.f32 "
        "{%0,%1,%2,%3}, {%4,%5,%6,%7}, {%8,%9}, {%0,%1,%2,%3};"
        : "+f"(c[0]), "+f"(c[1]), "+f"(c[2]), "+f"(c[3])
        : "r"(a.x), "r"(a.y), "r"(a.z), "r"(a.w), "r"(b.x), "r"(b.y));
}

// ---------------------------------------------------------------------------
// detect / prep
// ---------------------------------------------------------------------------
__global__ void detect_kernel(const int* __restrict__ seg32, int N) {
    int last = seg32[N - 1];
    int prev = seg32[N - 2];
    g_seg64 = (last == 0 && prev > 0) ? 1 : 0;
}

__global__ void prep_kernel(const float* __restrict__ Wq,
                            const float* __restrict__ Wk,
                            const float* __restrict__ bq,
                            const float* __restrict__ E, int B) {
    int tid = threadIdx.x;
    if (blockIdx.x == 0) {
        float s = 0.0f;
#pragma unroll 8
        for (int f = 0; f < FDIM; f++)
            s = fmaf(Wk[f], Wq[f * FDIM + tid], s);
        g_u[tid] = s;
        if (tid == 0) {
            float c = 0.0f;
            for (int f = 0; f < FDIM; f++) c = fmaf(bq[f], Wk[f], c);
            g_c0 = c;
        }
    } else {
        int b = (blockIdx.x - 1) * 256 + tid;
        if (b < B) {
            float e = fabsf(E[b]);
            g_ev[b] = e;
            g_cf[b] = e / fmaxf(e, 1.0f);
            g_anorm[b] = 0.0f;
        }
    }
}

// ---------------------------------------------------------------------------
// dot: 4 rows per warp, front-batched loads.
// ---------------------------------------------------------------------------
__global__ void dot_kernel(const float* __restrict__ x,
                           const void* __restrict__ seg, int N) {
    __shared__ float su[FDIM];
    __shared__ float sc0;
    int tid = threadIdx.x;
    su[tid] = g_u[tid];
    if (tid == 0) sc0 = g_c0;
    __syncthreads();

    int wid = tid >> 5, lane = tid & 31;
    int n0 = (blockIdx.x * 8 + wid) * 4;
    if (n0 >= N) return;

    float4 u0 = *(const float4*)&su[4 * lane];
    float4 u1 = *(const float4*)&su[128 + 4 * lane];

    float p[4];
#pragma unroll
    for (int r = 0; r < 4; r++) {
        int n = n0 + r;
        p[r] = 0.0f;
        if (n < N) {
            const float4* xr = (const float4*)(x + (size_t)n * FDIM);
            float4 xa = xr[lane];
            float4 xb = xr[32 + lane];
            p[r] = xa.x * u0.x + xa.y * u0.y + xa.z * u0.z + xa.w * u0.w +
                   xb.x * u1.x + xb.y * u1.y + xb.z * u1.z + xb.w * u1.w;
        }
    }
#pragma unroll
    for (int r = 0; r < 4; r++)
#pragma unroll
        for (int o = 16; o > 0; o >>= 1)
            p[r] += __shfl_down_sync(0xffffffffu, p[r], o);

    if (lane == 0) {
#pragma unroll
        for (int r = 0; r < 4; r++) {
            int n = n0 + r;
            if (n < N) {
                int b = get_seg(seg, n);
                float d = (p[r] + sc0) * g_cf[b] * 0.0625f;
                float a = fmaxf(d, 0.0f) + log1pf(expf(-fabsf(d)));
                g_a[n] = a;
                atomicAdd(&g_anorm[b], a);
            }
        }
    }
}

// ---------------------------------------------------------------------------
// convW: fp32 W[out][in] -> fragment-ordered fp16 chunk images.
// chunk layout: [t2(2)][j(32)][l(32)][2 uint32] = 16KB; chunks: [m(5)][c(8)].
// Index space: [m 5][c 8][t2 2][j 32][l 32] = 81920 threads.
// ---------------------------------------------------------------------------
#define CONVW_THREADS (5 * 8 * 2 * 32 * 32)   // 81920

__global__ void convW_kernel(const float* __restrict__ Wres1,
                             const float* __restrict__ Wres2,
                             const float* __restrict__ Wout) {
    int idx = blockIdx.x * blockDim.x + threadIdx.x;
    if (idx >= CONVW_THREADS) return;
    int l  = idx & 31;
    int j  = (idx >> 5) & 31;
    int t2 = (idx >> 10) & 1;
    int c  = (idx >> 11) & 7;
    int m  = idx >> 14;
    if (m >= 5) return;

    const float* Wm;
    switch (m) {
        case 0: Wm = Wres1; break;
        case 1: Wm = Wres2; break;
        case 2: Wm = Wres1 + 65536; break;
        case 3: Wm = Wres2 + 65536; break;
        default: Wm = Wout; break;
    }
    int n  = 8 * j + (l >> 2);
    int k0 = 32 * c + 16 * t2 + (l & 3) * 2;
    const float* p = Wm + n * FDIM + k0;
    uint32_t H0 = f16pack2(p[0], p[1]);
    uint32_t H1 = f16pack2(p[8], p[9]);
    size_t base = (size_t)(m * 8 + c) * CHUNK +
                  (size_t)(((t2 * 32 + j) * 32 + l)) * 8;
    *(uint2*)(g_Wf + base) = make_uint2(H0, H1);
}

// ---------------------------------------------------------------------------
// Epilogue store helper: totals -> silu -> fp16 A frags.
// ---------------------------------------------------------------------------
__device__ __forceinline__ void store_A_frags(const float Cm[2][8][4],
                                              unsigned char* aH,
                                              int m, int nh, int l) {
#pragma unroll
    for (int a = 0; a < 2; a++) {
#pragma unroll
        for (int tt = 0; tt < 4; tt++) {
            const float* X = Cm[a][2 * tt];
            const float* Y = Cm[a][2 * tt + 1];
            uint32_t H0 = f16pack2(siluf(X[0]), siluf(X[1]));
            uint32_t H1 = f16pack2(siluf(X[2]), siluf(X[3]));
            uint32_t H2 = f16pack2(siluf(Y[0]), siluf(Y[1]));
            uint32_t H3 = f16pack2(siluf(Y[2]), siluf(Y[3]));
            int slot = (2 * m + a) * 16 + 4 * nh + tt;
            size_t ao = (size_t)(slot * 32 + l) * 16;
            *(uint4*)(aH + ao) = make_uint4(H0, H1, H2, H3);
        }
    }
}

// ---------------------------------------------------------------------------
// chain_mma: 64 rows/CTA, 256 threads (8 warps). warp = (m = w>>2, nh = w&3)
// owning rows 32m..32m+31 x cols 64nh..64nh+63. Residual h in registers.
// SMEM: aH 32K | W ring 4x16K = 96K.
// ---------------------------------------------------------------------------
__global__ __launch_bounds__(256, 1)
void chain_mma(const void* __restrict__ seg,
               const float* __restrict__ Wv,
               float* __restrict__ out, int N) {
    extern __shared__ __align__(1024) unsigned char dyn[];
    unsigned char* aH = dyn;
    uint32_t wb_addr[RING];
    unsigned char* wb_ptr[RING];
#pragma unroll
    for (int i = 0; i < RING; i++) {
        wb_ptr[i] = dyn + 32768 + i * CHUNK;
        wb_addr[i] = smem_u32(wb_ptr[i]);
    }

    __shared__ __align__(8) unsigned long long s_mb[2 * RING];
    __shared__ float s_sv[TM];
    __shared__ float s_wv[FDIM];

    int tid = threadIdx.x;
    int w = tid >> 5, l = tid & 31;
    int m = w >> 2, nh = w & 3;
    int gid = l >> 2;
    int c2v = (l & 3) * 2;
    int r0 = blockIdx.x * TM;

    uint32_t mb_full[RING], mb_empty[RING];
#pragma unroll
    for (int i = 0; i < RING; i++) {
        mb_full[i]  = smem_u32(&s_mb[i]);
        mb_empty[i] = smem_u32(&s_mb[RING + i]);
    }

    if (tid == 0) {
#pragma unroll
        for (int i = 0; i < RING; i++) {
            mbar_init(mb_full[i], 1);
            mbar_init(mb_empty[i], 8);
        }
        FENCE_ASYNC();
    }
    if (tid < TM) {
        int n = r0 + tid;
        float s = 0.0f;
        if (n < N) {
            int b = get_seg(seg, n);
            s = g_a[n] / (g_anorm[b] + 1e-8f) * g_ev[b];
        }
        s_sv[tid] = s;
    }
    s_wv[tid] = Wv[tid];
    __syncthreads();

    if (tid == 0) {
#pragma unroll
        for (int i = 0; i < RING; i++) {
            mbar_expect(mb_full[i], CHUNK);
            bulk_g2s(wb_addr[i], g_Wf + (size_t)i * CHUNK, CHUNK, mb_full[i]);
        }
    }

    float Cm[2][8][4];   // accumulator / current activation tile
    float hR[2][8][4];   // residual h (warp-private, register-resident)

    // ---- init: h0 = s (x) Wv into Cm; hR = Cm; store A = f16(silu(h0)).
    {
#pragma unroll
        for (int a = 0; a < 2; a++) {
            int rlo = 16 * (2 * m + a) + gid;
            float s0 = s_sv[rlo];
            float s1 = s_sv[rlo + 8];
#pragma unroll
            for (int jj = 0; jj < 8; jj++) {
                int col = 8 * (8 * nh + jj) + c2v;
                float w0 = s_wv[col], w1 = s_wv[col + 1];
                Cm[a][jj][0] = s0 * w0;
                Cm[a][jj][1] = s0 * w1;
                Cm[a][jj][2] = s1 * w0;
                Cm[a][jj][3] = s1 * w1;
                hR[a][jj][0] = Cm[a][jj][0];
                hR[a][jj][1] = Cm[a][jj][1];
                hR[a][jj][2] = Cm[a][jj][2];
                hR[a][jj][3] = Cm[a][jj][3];
            }
        }
        store_A_frags(Cm, aH, m, nh, l);
    }
    __syncthreads();

#pragma unroll 1
    for (int g = 0; g < 5; g++) {
        // ---- accumulator init: residual GEMMs start from h
        if (g == 1 || g == 3) {
#pragma unroll
            for (int a = 0; a < 2; a++)
#pragma unroll
                for (int jj = 0; jj < 8; jj++) {
                    Cm[a][jj][0] = hR[a][jj][0];
                    Cm[a][jj][1] = hR[a][jj][1];
                    Cm[a][jj][2] = hR[a][jj][2];
                    Cm[a][jj][3] = hR[a][jj][3];
                }
        } else {
#pragma unroll
            for (int a = 0; a < 2; a++)
#pragma unroll
                for (int jj = 0; jj < 8; jj++)
                    Cm[a][jj][0] = Cm[a][jj][1] = Cm[a][jj][2] = Cm[a][jj][3] = 0.0f;
        }

        // ---- mainloop: 8 k-chunks of 32
#pragma unroll 1
        for (int c = 0; c < 8; c++) {
            int q = 8 * g + c;
            int s = q & (RING - 1);
            mbar_wait(mb_full[s], (uint32_t)((q >> 2) & 1));
            const unsigned char* wt = wb_ptr[s] + (size_t)l * 8 + nh * 2048;

#pragma unroll
            for (int t = 0; t < 2; t++) {
                int slot0 = (2 * m + 0) * 16 + 2 * c + t;
                int slot1 = (2 * m + 1) * 16 + 2 * c + t;
                uint4 ah0 = *(const uint4*)(aH + (size_t)(slot0 * 32 + l) * 16);
                uint4 ah1 = *(const uint4*)(aH + (size_t)(slot1 * 32 + l) * 16);
                const unsigned char* wtt = wt + t * 8192;
#pragma unroll
                for (int jj = 0; jj < 8; jj++) {
                    uint2 bh = *(const uint2*)(wtt + jj * 256);
                    mma_f32(Cm[0][jj], ah0, bh);
                    mma_f32(Cm[1][jj], ah1, bh);
                }
            }
            if (l == 0) mbar_arrive(mb_empty[s]);
            if (tid == 0 && q + RING < NQ) {
                int qq = q + RING;
                int fs = qq & (RING - 1);
                mbar_wait(mb_empty[fs], (uint32_t)(((qq >> 2) + 1) & 1));
                mbar_expect(mb_full[fs], CHUNK);
                bulk_g2s(wb_addr[fs], g_Wf + (size_t)qq * CHUNK, CHUNK,
                         mb_full[fs]);
            }
        }

        BAR_NAMED(1 + m, 128);   // m-group done reading A

        // ---- epilogue
        if (g == 4) {
#pragma unroll
            for (int a = 0; a < 2; a++) {
                int rlo = r0 + 16 * (2 * m + a) + gid;
#pragma unroll
                for (int jj = 0; jj < 8; jj++) {
                    int col = 8 * (8 * nh + jj) + c2v;
                    if (rlo < N)
                        *(float2*)(out + (size_t)rlo * FDIM + col) =
                            make_float2(Cm[a][jj][0], Cm[a][jj][1]);
                    if (rlo + 8 < N)
                        *(float2*)(out + (size_t)(rlo + 8) * FDIM + col) =
                            make_float2(Cm[a][jj][2], Cm[a][jj][3]);
                }
            }
        } else {
            if (g == 1 || g == 3) {   // h updated: hR = Cm
#pragma unroll
                for (int a = 0; a < 2; a++)
#pragma unroll
                    for (int jj = 0; jj < 8; jj++) {
                        hR[a][jj][0] = Cm[a][jj][0];
                        hR[a][jj][1] = Cm[a][jj][1];
                        hR[a][jj][2] = Cm[a][jj][2];
                        hR[a][jj][3] = Cm[a][jj][3];
                    }
            }
            store_A_frags(Cm, aH, m, nh, l);
            BAR_NAMED(1 + m, 128);   // publish A before next GEMM reads
        }
    }
}

// ---------------------------------------------------------------------------
extern "C" void kernel_launch(void* const* d_in, const int* in_sizes, int n_in,
                              void* d_out, int out_size) {
    int base = (n_in >= 11 && in_sizes[2] == 1) ? 1 : 0;

    const float* x     = (const float*)d_in[0];
    const float* E     = (const float*)d_in[1];
    const void*  seg   = d_in[2 + base];
    const float* Wq    = (const float*)d_in[3 + base];
    const float* bq    = (const float*)d_in[4 + base];
    const float* Wk    = (const float*)d_in[5 + base];
    const float* Wv    = (const float*)d_in[6 + base];
    const float* Wres1 = (const float*)d_in[7 + base];
    const float* Wres2 = (const float*)d_in[8 + base];
    const float* Wout  = (const float*)d_in[9 + base];

    int N = in_sizes[0] / FDIM;
    int B = in_sizes[1];
    if (N > MAXN) N = MAXN;
    if (B > MAXB) B = MAXB;

    detect_kernel<<<1, 1>>>((const int*)seg, N);
    prep_kernel<<<1 + (B + 255) / 256, 256>>>(Wq, Wk, bq, E, B);
    convW_kernel<<<(CONVW_THREADS + 127) / 128, 128>>>(Wres1, Wres2, Wout);
    dot_kernel<<<(N + 31) / 32, 256>>>(x, seg, N);

    int smem_bytes = 32768 + RING * CHUNK;   // 96 KB
    cudaFuncSetAttribute(chain_mma, cudaFuncAttributeMaxDynamicSharedMemorySize,
                         smem_bytes);
    chain_mma<<<(N + TM - 1) / TM, 256, smem_bytes>>>(seg, Wv, (float*)d_out, N);
}